// round 1
// baseline (speedup 1.0000x reference)
#include <cuda_runtime.h>

#define B_     8
#define N_     16384
#define HM_    128
#define WM_    128
#define DIM_   128
#define HEADS_ 8
#define DH_    64
#define INNER_ 512
#define G_     64

// ---------------- scratch (device globals; no runtime allocation) ----------
__device__ float g_fx[67108864];   // (B,N,512)  conv_fx output
__device__ float g_xm[67108864];   // (B,N,512)  conv_x  output
__device__ float g_sw[67108864];   // (B,N,H,64) slice weights
__device__ float g_ox[67108864];   // (B,N,512)  out_x
__device__ float g_part[4194304];  // 16 chunks x 64 bh x 4096 slice_token partials
__device__ float g_npart[65536];   // 16 chunks x 64 bh x 64 norm partials
__device__ float g_st[262144];     // raw slice_token (64 bh x 64 g x 64 c)
__device__ float g_norm[4096];     // (64 bh x 64 g)
__device__ float g_q[262144];
__device__ float g_k[262144];
__device__ float g_v[262144];
__device__ float g_os[262144];     // out_slice

// ---------------- conv: implicit GEMM, both convs fused in cout dim --------
// grid.x = 2048 pixel tiles (64 px each), grid.y = 16 cout tiles (64 each,
// tiles 0..7 -> conv_fx, 8..15 -> conv_x). block = 256 threads, 4x4 micro.
__global__ void conv_kernel(const float* __restrict__ x,
                            const float* __restrict__ wfx, const float* __restrict__ bfx,
                            const float* __restrict__ wx,  const float* __restrict__ bx)
{
    __shared__ float As[32][68];   // [k][pixel]
    __shared__ float Bs[32][64];   // [k][cout]

    int tid = threadIdx.x;
    int ptile = blockIdx.x;
    int b  = ptile >> 8;           // 256 pixel tiles per batch image
    int n0 = (ptile & 255) * 64;
    int y  = n0 >> 7;              // all 64 pixels share the same row y
    int x0 = n0 & 127;

    int cot = blockIdx.y * 64;
    const float* w; const float* bias; float* outp;
    if (cot < 512) { w = wfx; bias = bfx; outp = g_fx; }
    else           { w = wx;  bias = bx;  outp = g_xm; cot -= 512; }

    float acc[4][4] = {};
    int ty = tid >> 4, tx = tid & 15;

    for (int tap = 0; tap < 9; ++tap) {
        int dy = tap / 3 - 1, dx = tap % 3 - 1;
        int yy = y + dy;
        if ((unsigned)yy >= 128u) continue;        // uniform across block
        const float* xrow = x + ((size_t)(b * N_ + yy * WM_)) * DIM_;

        for (int cc = 0; cc < 4; ++cc) {
            int ci0 = cc * 32;
            // A tile: 64 px x 32 ci, stored transposed
            #pragma unroll
            for (int i = 0; i < 2; ++i) {
                int f = tid + 256 * i;
                int r = f >> 3;
                int c4 = f & 7;
                int xin = x0 + r + dx;
                float4 v = make_float4(0.f, 0.f, 0.f, 0.f);
                if ((unsigned)xin < 128u)
                    v = *(const float4*)(xrow + (size_t)xin * DIM_ + ci0 + c4 * 4);
                As[c4 * 4 + 0][r] = v.x;
                As[c4 * 4 + 1][r] = v.y;
                As[c4 * 4 + 2][r] = v.z;
                As[c4 * 4 + 3][r] = v.w;
            }
            // B tile: 32 ci x 64 co (w layout: (3,3,128,512), co contiguous)
            #pragma unroll
            for (int i = 0; i < 2; ++i) {
                int f = tid + 256 * i;
                int c  = f >> 4;
                int g4 = f & 15;
                float4 v = *(const float4*)(w + ((size_t)(tap * 128 + ci0 + c)) * 512
                                              + cot + g4 * 4);
                *(float4*)&Bs[c][g4 * 4] = v;
            }
            __syncthreads();
            #pragma unroll
            for (int kk = 0; kk < 32; ++kk) {
                float4 a  = *(const float4*)&As[kk][ty * 4];
                float4 bv = *(const float4*)&Bs[kk][tx * 4];
                acc[0][0] += a.x * bv.x; acc[0][1] += a.x * bv.y;
                acc[0][2] += a.x * bv.z; acc[0][3] += a.x * bv.w;
                acc[1][0] += a.y * bv.x; acc[1][1] += a.y * bv.y;
                acc[1][2] += a.y * bv.z; acc[1][3] += a.y * bv.w;
                acc[2][0] += a.z * bv.x; acc[2][1] += a.z * bv.y;
                acc[2][2] += a.z * bv.z; acc[2][3] += a.z * bv.w;
                acc[3][0] += a.w * bv.x; acc[3][1] += a.w * bv.y;
                acc[3][2] += a.w * bv.z; acc[3][3] += a.w * bv.w;
            }
            __syncthreads();
        }
    }
    #pragma unroll
    for (int i = 0; i < 4; ++i) {
        int n = n0 + ty * 4 + i;
        float* o = outp + ((size_t)(b * N_ + n)) * 512 + cot + tx * 4;
        #pragma unroll
        for (int j = 0; j < 4; ++j)
            o[j] = acc[i][j] + bias[cot + tx * 4 + j];
    }
}

// ---------------- slice weights: softmax over G, one warp per (b,n,h) ------
__global__ void sliceweights_kernel(const float* __restrict__ slice_w,
                                    const float* __restrict__ slice_b,
                                    const float* __restrict__ temperature)
{
    __shared__ float sm[8][64];
    int warp = threadIdx.x >> 5;
    int lane = threadIdx.x & 31;
    int gw = blockIdx.x * 8 + warp;          // < 1048576
    int h  = gw & 7;
    int bn = gw >> 3;                        // b*N + n

    float* m = sm[warp];
    const float* xm = g_xm + (size_t)bn * 512 + h * 64;
    m[lane] = xm[lane];
    m[lane + 32] = xm[lane + 32];
    __syncwarp();

    float t = temperature[h];
    t = fminf(fmaxf(t, 0.1f), 5.0f);

    float l0 = slice_b[lane], l1 = slice_b[lane + 32];
    const float* w0 = slice_w + lane * 64;
    const float* w1 = slice_w + (lane + 32) * 64;
    #pragma unroll 8
    for (int c = 0; c < 64; ++c) {
        float mv = m[c];
        l0 += mv * w0[c];
        l1 += mv * w1[c];
    }
    l0 /= t; l1 /= t;
    float mx = fmaxf(l0, l1);
    #pragma unroll
    for (int o = 16; o; o >>= 1) mx = fmaxf(mx, __shfl_xor_sync(0xffffffffu, mx, o));
    float e0 = __expf(l0 - mx), e1 = __expf(l1 - mx);
    float s = e0 + e1;
    #pragma unroll
    for (int o = 16; o; o >>= 1) s += __shfl_xor_sync(0xffffffffu, s, o);
    float inv = 1.f / s;
    float* out = g_sw + ((size_t)bn * 8 + h) * 64;
    out[lane] = e0 * inv;
    out[lane + 32] = e1 * inv;
}

// ---------------- slice_token split-K partials (no atomics) ----------------
// grid (64 bh, 16 chunks of 1024 n), block 256. Thread owns (g, 16 c's).
__global__ void slicetoken_kernel()
{
    __shared__ float Ws[4][64];
    __shared__ float Fs[4][64];
    int bh = blockIdx.x;
    int chunk = blockIdx.y;
    int b = bh >> 3, h = bh & 7;
    int tid = threadIdx.x;
    int g = tid & 63;
    int cb = (tid >> 6) * 16;

    float acc[16] = {};
    float nacc = 0.f;
    size_t nbase = (size_t)b * N_ + chunk * 1024;

    for (int n4 = 0; n4 < 1024; n4 += 4) {
        int j = tid >> 6;
        int c = tid & 63;
        size_t n = nbase + n4 + j;
        Ws[j][c] = g_sw[(n * 8 + h) * 64 + c];
        Fs[j][c] = g_fx[n * 512 + h * 64 + c];
        __syncthreads();
        #pragma unroll
        for (int j2 = 0; j2 < 4; ++j2) {
            float wv = Ws[j2][g];
            if (tid < 64) nacc += wv;
            float4 f0 = *(const float4*)&Fs[j2][cb + 0];
            float4 f1 = *(const float4*)&Fs[j2][cb + 4];
            float4 f2 = *(const float4*)&Fs[j2][cb + 8];
            float4 f3 = *(const float4*)&Fs[j2][cb + 12];
            acc[0]  += wv * f0.x; acc[1]  += wv * f0.y; acc[2]  += wv * f0.z; acc[3]  += wv * f0.w;
            acc[4]  += wv * f1.x; acc[5]  += wv * f1.y; acc[6]  += wv * f1.z; acc[7]  += wv * f1.w;
            acc[8]  += wv * f2.x; acc[9]  += wv * f2.y; acc[10] += wv * f2.z; acc[11] += wv * f2.w;
            acc[12] += wv * f3.x; acc[13] += wv * f3.y; acc[14] += wv * f3.z; acc[15] += wv * f3.w;
        }
        __syncthreads();
    }
    float* p = g_part + ((size_t)chunk * 64 + bh) * 4096 + g * 64 + cb;
    #pragma unroll
    for (int q = 0; q < 16; ++q) p[q] = acc[q];
    if (tid < 64) g_npart[(chunk * 64 + bh) * 64 + tid] = nacc;
}

// ---------------- reduce partials -------------------------------------------
__global__ void reduce_token_kernel()
{
    int idx = blockIdx.x * 512 + threadIdx.x;   // < 262144
    float s = 0.f;
    #pragma unroll
    for (int ch = 0; ch < 16; ++ch) s += g_part[(size_t)ch * 262144 + idx];
    g_st[idx] = s;
    if (idx < 4096) {
        float ns = 0.f;
        #pragma unroll
        for (int ch = 0; ch < 16; ++ch) ns += g_npart[ch * 4096 + idx];
        g_norm[idx] = ns;
    }
}

// ---------------- normalize + QKV projections, block per (b,h) --------------
__global__ void qkv_kernel(const float* __restrict__ wq,
                           const float* __restrict__ wk,
                           const float* __restrict__ wv)
{
    __shared__ float S[64][65];
    int bh = blockIdx.x;
    int tid = threadIdx.x;
    const float* st = g_st + (size_t)bh * 4096;
    const float* nm = g_norm + bh * 64;
    for (int i = tid; i < 4096; i += 256)
        S[i >> 6][i & 63] = st[i] / (nm[i >> 6] + 1e-5f);
    __syncthreads();

    int g = tid >> 2;
    int d0 = (tid & 3) * 16;
    for (int d = d0; d < d0 + 16; ++d) {
        float q = 0.f, k = 0.f, v = 0.f;
        #pragma unroll 8
        for (int c = 0; c < 64; ++c) {
            float s = S[g][c];
            q += s * wq[d * 64 + c];
            k += s * wk[d * 64 + c];
            v += s * wv[d * 64 + c];
        }
        int o = bh * 4096 + g * 64 + d;
        g_q[o] = q; g_k[o] = k; g_v[o] = v;
    }
}

// ---------------- 64x64 attention per (b,h) ---------------------------------
__global__ void attn_kernel()
{
    __shared__ float X[64][65];   // Q, then attn matrix
    __shared__ float Y[64][65];   // K, then V
    int bh = blockIdx.x;
    int tid = threadIdx.x;
    for (int i = tid; i < 4096; i += 256) {
        X[i >> 6][i & 63] = g_q[bh * 4096 + i];
        Y[i >> 6][i & 63] = g_k[bh * 4096 + i];
    }
    __syncthreads();

    int g = tid >> 2;
    int k0 = (tid & 3) * 16;
    float a[16];
    #pragma unroll
    for (int i = 0; i < 16; ++i) {
        float s = 0.f;
        for (int c = 0; c < 64; ++c) s += X[g][c] * Y[k0 + i][c];
        a[i] = s * 0.125f;            // DH^-0.5
    }
    __syncthreads();
    #pragma unroll
    for (int i = 0; i < 16; ++i) X[g][k0 + i] = a[i];
    for (int i = tid; i < 4096; i += 256)
        Y[i >> 6][i & 63] = g_v[bh * 4096 + i];
    __syncthreads();

    if (tid < 64) {
        float mx = -1e30f;
        for (int k = 0; k < 64; ++k) mx = fmaxf(mx, X[tid][k]);
        float s = 0.f;
        for (int k = 0; k < 64; ++k) { float e = __expf(X[tid][k] - mx); X[tid][k] = e; s += e; }
        float inv = 1.f / s;
        for (int k = 0; k < 64; ++k) X[tid][k] *= inv;
    }
    __syncthreads();

    for (int d = k0; d < k0 + 16; ++d) {
        float o = 0.f;
        for (int k = 0; k < 64; ++k) o += X[g][k] * Y[k][d];
        g_os[bh * 4096 + g * 64 + d] = o;
    }
}

// ---------------- out_x = out_slice scattered back through slice weights ----
// grid (256 n-tiles, 64 bh), block 256, 4x4 micro, K = G = 64.
__global__ void outx_kernel()
{
    __shared__ float SWt[64][68];  // [g][n]
    __shared__ float OS[64][64];   // [g][c]
    int ntile = blockIdx.x;
    int bh = blockIdx.y;
    int b = bh >> 3, h = bh & 7;
    int n0 = ntile * 64;
    int tid = threadIdx.x;

    #pragma unroll
    for (int i = 0; i < 4; ++i) {
        int f = tid + 256 * i;         // 1024 float4
        int n = f >> 4;
        int gg = (f & 15) * 4;
        float4 v = *(const float4*)(g_sw + ((size_t)(b * N_ + n0 + n) * 8 + h) * 64 + gg);
        SWt[gg + 0][n] = v.x;
        SWt[gg + 1][n] = v.y;
        SWt[gg + 2][n] = v.z;
        SWt[gg + 3][n] = v.w;
    }
    #pragma unroll
    for (int i = 0; i < 4; ++i) {
        int f = tid + 256 * i;
        int gg = f >> 4;
        int c4 = f & 15;
        *(float4*)&OS[gg][c4 * 4] = *(const float4*)(g_os + (size_t)bh * 4096 + gg * 64 + c4 * 4);
    }
    __syncthreads();

    int ty = tid >> 4, tx = tid & 15;
    float acc[4][4] = {};
    #pragma unroll
    for (int kk = 0; kk < 64; ++kk) {
        float4 a  = *(const float4*)&SWt[kk][ty * 4];
        float4 bv = *(const float4*)&OS[kk][tx * 4];
        acc[0][0] += a.x * bv.x; acc[0][1] += a.x * bv.y; acc[0][2] += a.x * bv.z; acc[0][3] += a.x * bv.w;
        acc[1][0] += a.y * bv.x; acc[1][1] += a.y * bv.y; acc[1][2] += a.y * bv.z; acc[1][3] += a.y * bv.w;
        acc[2][0] += a.z * bv.x; acc[2][1] += a.z * bv.y; acc[2][2] += a.z * bv.z; acc[2][3] += a.z * bv.w;
        acc[3][0] += a.w * bv.x; acc[3][1] += a.w * bv.y; acc[3][2] += a.w * bv.z; acc[3][3] += a.w * bv.w;
    }
    #pragma unroll
    for (int i = 0; i < 4; ++i) {
        int n = n0 + ty * 4 + i;
        float* o = g_ox + ((size_t)(b * N_ + n)) * 512 + h * 64 + tx * 4;
        #pragma unroll
        for (int j = 0; j < 4; ++j) o[j] = acc[i][j];
    }
}

// ---------------- final projection GEMM (131072 x 128, K=512) ---------------
__global__ void final_kernel(const float* __restrict__ out_w,
                             const float* __restrict__ out_b,
                             float* __restrict__ out)
{
    __shared__ float As[32][68];   // [k][m]
    __shared__ float Bs[32][68];   // [k][d]
    int m0 = blockIdx.x * 64;      // over b*N
    int d0 = blockIdx.y * 64;
    int tid = threadIdx.x;
    int ty = tid >> 4, tx = tid & 15;
    float acc[4][4] = {};

    for (int k0 = 0; k0 < 512; k0 += 32) {
        #pragma unroll
        for (int i = 0; i < 2; ++i) {
            int f = tid + 256 * i;
            int r = f >> 3;
            int kg = f & 7;
            float4 v = *(const float4*)(g_ox + (size_t)(m0 + r) * 512 + k0 + kg * 4);
            As[kg * 4 + 0][r] = v.x;
            As[kg * 4 + 1][r] = v.y;
            As[kg * 4 + 2][r] = v.z;
            As[kg * 4 + 3][r] = v.w;
        }
        #pragma unroll
        for (int i = 0; i < 2; ++i) {
            int f = tid + 256 * i;
            int dd = f >> 3;
            int kg = f & 7;
            float4 v = *(const float4*)(out_w + (size_t)(d0 + dd) * 512 + k0 + kg * 4);
            Bs[kg * 4 + 0][dd] = v.x;
            Bs[kg * 4 + 1][dd] = v.y;
            Bs[kg * 4 + 2][dd] = v.z;
            Bs[kg * 4 + 3][dd] = v.w;
        }
        __syncthreads();
        #pragma unroll
        for (int kk = 0; kk < 32; ++kk) {
            float4 a  = *(const float4*)&As[kk][ty * 4];
            float4 bv = *(const float4*)&Bs[kk][tx * 4];
            acc[0][0] += a.x * bv.x; acc[0][1] += a.x * bv.y; acc[0][2] += a.x * bv.z; acc[0][3] += a.x * bv.w;
            acc[1][0] += a.y * bv.x; acc[1][1] += a.y * bv.y; acc[1][2] += a.y * bv.z; acc[1][3] += a.y * bv.w;
            acc[2][0] += a.z * bv.x; acc[2][1] += a.z * bv.y; acc[2][2] += a.z * bv.z; acc[2][3] += a.z * bv.w;
            acc[3][0] += a.w * bv.x; acc[3][1] += a.w * bv.y; acc[3][2] += a.w * bv.z; acc[3][3] += a.w * bv.w;
        }
        __syncthreads();
    }
    #pragma unroll
    for (int i = 0; i < 4; ++i) {
        int m = m0 + ty * 4 + i;
        float* o = out + (size_t)m * 128 + d0 + tx * 4;
        #pragma unroll
        for (int j = 0; j < 4; ++j)
            o[j] = acc[i][j] + out_b[d0 + tx * 4 + j];
    }
}

// ---------------- launch -----------------------------------------------------
extern "C" void kernel_launch(void* const* d_in, const int* in_sizes, int n_in,
                              void* d_out, int out_size)
{
    const float* x          = (const float*)d_in[0];
    const float* conv_fx_w  = (const float*)d_in[1];
    const float* conv_fx_b  = (const float*)d_in[2];
    const float* conv_x_w   = (const float*)d_in[3];
    const float* conv_x_b   = (const float*)d_in[4];
    const float* slice_w    = (const float*)d_in[5];
    const float* slice_b    = (const float*)d_in[6];
    const float* temperature= (const float*)d_in[7];
    const float* wq         = (const float*)d_in[8];
    const float* wk         = (const float*)d_in[9];
    const float* wv         = (const float*)d_in[10];
    const float* out_w      = (const float*)d_in[11];
    const float* out_b      = (const float*)d_in[12];
    float* out = (float*)d_out;

    conv_kernel<<<dim3(2048, 16), 256>>>(x, conv_fx_w, conv_fx_b, conv_x_w, conv_x_b);
    sliceweights_kernel<<<131072, 256>>>(slice_w, slice_b, temperature);
    slicetoken_kernel<<<dim3(64, 16), 256>>>();
    reduce_token_kernel<<<512, 512>>>();
    qkv_kernel<<<64, 256>>>(wq, wk, wv);
    attn_kernel<<<64, 256>>>();
    outx_kernel<<<dim3(256, 64), 256>>>();
    final_kernel<<<dim3(2048, 2), 256>>>(out_w, out_b, out);
}

// round 3
// speedup vs baseline: 1.3466x; 1.3466x over previous
#include <cuda_runtime.h>

#define B_     8
#define N_     16384
#define DIM_   128
#define HEADS_ 8
#define DH_    64
#define INNER_ 512
#define G_     64

// ---------------- scratch (device globals; no runtime allocation) ----------
__device__ float g_fx[67108864];   // (B,N,512)  conv_fx output
__device__ float g_xm[67108864];   // (B,N,512)  conv_x  output
__device__ float g_sw[67108864];   // (B,N,H,64) slice weights
__device__ float g_ox[67108864];   // (B,N,512)  out_x
__device__ float g_part[4194304];
__device__ float g_npart[65536];
__device__ float g_st[262144];
__device__ float g_norm[4096];
__device__ float g_q[262144];
__device__ float g_k[262144];
__device__ float g_v[262144];
__device__ float g_os[262144];
__device__ float g_wt[1179648];    // transposed tf32-rounded weights [1024 co][1152 k]

__device__ __forceinline__ unsigned cvt_tf32(float f) {
    unsigned u;
    asm("cvt.rna.tf32.f32 %0, %1;" : "=r"(u) : "f"(f));
    return u;
}
__device__ __forceinline__ unsigned smem_u32(const void* p) {
    unsigned a;
    asm("{ .reg .u64 t; cvta.to.shared.u64 t, %1; cvt.u32.u64 %0, t; }"
        : "=r"(a) : "l"(p));
    return a;
}
__device__ __forceinline__ void mma_tf32(float* c, const unsigned* a, const unsigned* b) {
    asm volatile("mma.sync.aligned.m16n8k8.row.col.f32.tf32.tf32.f32 "
                 "{%0,%1,%2,%3}, {%4,%5,%6,%7}, {%8,%9}, {%0,%1,%2,%3};"
                 : "+f"(c[0]), "+f"(c[1]), "+f"(c[2]), "+f"(c[3])
                 : "r"(a[0]), "r"(a[1]), "r"(a[2]), "r"(a[3]),
                   "r"(b[0]), "r"(b[1]));
}

// ---------------- weight transpose + tf32 rounding --------------------------
__global__ void wprep_kernel(const float* __restrict__ wfx,
                             const float* __restrict__ wx)
{
    int idx = blockIdx.x * 256 + threadIdx.x;          // < 1024*1152
    if (idx >= 1179648) return;
    int co = idx / 1152;
    int k  = idx - co * 1152;
    const float* w = (co < 512) ? wfx : wx;
    int c = (co < 512) ? co : co - 512;
    float v = w[(size_t)k * 512 + c];
    g_wt[idx] = __uint_as_float(cvt_tf32(v));
}

// ---------------- conv via tf32 mma.sync ------------------------------------
// grid (1024 rows, 8 cout-tiles of 128), 256 threads (8 warps, 2Mx4N).
// CTA tile: 128 px x 128 co, K=1152 in 36 chunks of 32. Double-buffered smem.
// Stage: A[128][36] floats (18432B) + B[128][36] (18432B) = 36864B; x2 stages.
__global__ void __launch_bounds__(256, 2)
conv_mma_kernel(const float* __restrict__ x,
                const float* __restrict__ bfx, const float* __restrict__ bx)
{
    extern __shared__ float sm[];
    const int tid  = threadIdx.x;
    const int wid  = tid >> 5;
    const int lane = tid & 31;
    const int g    = lane >> 2;
    const int t4   = lane & 3;
    const int warpM = wid & 1;
    const int warpN = wid >> 1;

    const int row = blockIdx.x;          // b*128 + y
    const int b   = row >> 7;
    const int y   = row & 127;
    const int ct  = blockIdx.y;          // 0..7 (0-3 fx, 4-7 xm)
    const int co0 = ct * 128;            // fused cout base (0..1023)

    const float* xrowbase = x + (size_t)b * (N_ * DIM_);

    float acc[4][4][4] = {};
    uint4 av[4];

    const int fr = tid >> 1;                    // unused helper removed
    (void)fr;

    // --- A prefetch for chunk c into av[] ---
    auto prefetchA = [&](int c) {
        const int tap = c >> 2;
        const int dy = tap / 3 - 1, dx = tap % 3 - 1;
        const int yy = y + dy;
        const bool rowok = (unsigned)yy < 128u;
        const int ci0 = (c & 3) * 32;
        #pragma unroll
        for (int i = 0; i < 4; ++i) {
            int f = tid + 256 * i;
            int r = f >> 3, q = f & 7;
            int xp = r + dx;
            uint4 v = make_uint4(0u, 0u, 0u, 0u);
            if (rowok && (unsigned)xp < 128u) {
                float4 fv = *(const float4*)(xrowbase + ((size_t)yy * 128 + xp) * 128
                                             + ci0 + q * 4);
                v.x = cvt_tf32(fv.x); v.y = cvt_tf32(fv.y);
                v.z = cvt_tf32(fv.z); v.w = cvt_tf32(fv.w);
            }
            av[i] = v;
        }
    };
    auto storeA = [&](int s) {
        float* As_ = sm + s * 9216;
        #pragma unroll
        for (int i = 0; i < 4; ++i) {
            int f = tid + 256 * i;
            int r = f >> 3, q = f & 7;
            *(uint4*)(As_ + r * 36 + q * 4) = av[i];
        }
    };
    auto cpasyncB = [&](int c, int s) {
        float* Bs_ = sm + s * 9216 + 4608;
        const int k0w = (c >> 2) * 128 + (c & 3) * 32;
        #pragma unroll
        for (int i = 0; i < 4; ++i) {
            int f = tid + 256 * i;
            int r = f >> 3, q = f & 7;
            const float* src = g_wt + (size_t)(co0 + r) * 1152 + k0w + q * 4;
            unsigned dst = smem_u32(Bs_ + r * 36 + q * 4);
            asm volatile("cp.async.cg.shared.global [%0], [%1], 16;"
                         :: "r"(dst), "l"(src));
        }
    };
    auto compute = [&](int s) {
        const float* As_ = sm + s * 9216;
        const float* Bs_ = As_ + 4608;
        const int m0 = warpM * 64;
        const int n0 = warpN * 32;
        #pragma unroll
        for (int ks = 0; ks < 4; ++ks) {
            const int kk = ks * 8;
            unsigned af[4][4];
            #pragma unroll
            for (int mt = 0; mt < 4; ++mt) {
                const float* p0 = As_ + (m0 + mt * 16 + g) * 36 + kk + t4;
                const float* p1 = p0 + 8 * 36;
                af[mt][0] = __float_as_uint(p0[0]);
                af[mt][1] = __float_as_uint(p1[0]);
                af[mt][2] = __float_as_uint(p0[4]);
                af[mt][3] = __float_as_uint(p1[4]);
            }
            unsigned bf[4][2];
            #pragma unroll
            for (int nt = 0; nt < 4; ++nt) {
                const float* p = Bs_ + (n0 + nt * 8 + g) * 36 + kk + t4;
                bf[nt][0] = __float_as_uint(p[0]);
                bf[nt][1] = __float_as_uint(p[4]);
            }
            #pragma unroll
            for (int mt = 0; mt < 4; ++mt)
                #pragma unroll
                for (int nt = 0; nt < 4; ++nt)
                    mma_tf32(acc[mt][nt], af[mt], bf[nt]);
        }
    };

    // --- pipeline ---
    prefetchA(0);
    storeA(0);
    cpasyncB(0, 0);
    asm volatile("cp.async.commit_group;");
    prefetchA(1);
    asm volatile("cp.async.wait_group 0;");
    __syncthreads();

    for (int c = 0; c < 36; ++c) {
        const int s = c & 1;
        if (c < 35) {
            storeA(s ^ 1);
            cpasyncB(c + 1, s ^ 1);
            asm volatile("cp.async.commit_group;");
        }
        if (c < 34) prefetchA(c + 2);
        compute(s);
        if (c < 35) {
            asm volatile("cp.async.wait_group 0;");
            __syncthreads();
        }
    }

    // --- epilogue ---
    float* outp = (ct < 4) ? g_fx : g_xm;
    const float* biasp = ((ct < 4) ? bfx : bx) + (ct & 3) * 128;
    const size_t rowbase = (size_t)row * 128 * 512 + (ct & 3) * 128;

    #pragma unroll
    for (int mt = 0; mt < 4; ++mt) {
        const int m = warpM * 64 + mt * 16 + g;
        #pragma unroll
        for (int nt = 0; nt < 4; ++nt) {
            const int nl = warpN * 32 + nt * 8 + t4 * 2;
            float b0 = __ldg(biasp + nl), b1 = __ldg(biasp + nl + 1);
            float2 v0 = make_float2(acc[mt][nt][0] + b0, acc[mt][nt][1] + b1);
            float2 v1 = make_float2(acc[mt][nt][2] + b0, acc[mt][nt][3] + b1);
            *(float2*)(outp + rowbase + (size_t)m * 512 + nl) = v0;
            *(float2*)(outp + rowbase + (size_t)(m + 8) * 512 + nl) = v1;
        }
    }
}

// ---------------- slice weights: softmax over G, one warp per (b,n,h) ------
__global__ void sliceweights_kernel(const float* __restrict__ slice_w,
                                    const float* __restrict__ slice_b,
                                    const float* __restrict__ temperature)
{
    __shared__ float smm[8][64];
    int warp = threadIdx.x >> 5;
    int lane = threadIdx.x & 31;
    int gw = blockIdx.x * 8 + warp;
    int h  = gw & 7;
    int bn = gw >> 3;

    float* m = smm[warp];
    const float* xm = g_xm + (size_t)bn * 512 + h * 64;
    m[lane] = xm[lane];
    m[lane + 32] = xm[lane + 32];
    __syncwarp();

    float tv = temperature[h];
    tv = fminf(fmaxf(tv, 0.1f), 5.0f);

    float l0 = slice_b[lane], l1 = slice_b[lane + 32];
    const float* w0 = slice_w + lane * 64;
    const float* w1 = slice_w + (lane + 32) * 64;
    #pragma unroll 8
    for (int c = 0; c < 64; ++c) {
        float mv = m[c];
        l0 += mv * w0[c];
        l1 += mv * w1[c];
    }
    l0 /= tv; l1 /= tv;
    float mx = fmaxf(l0, l1);
    #pragma unroll
    for (int o = 16; o; o >>= 1) mx = fmaxf(mx, __shfl_xor_sync(0xffffffffu, mx, o));
    float e0 = __expf(l0 - mx), e1 = __expf(l1 - mx);
    float s = e0 + e1;
    #pragma unroll
    for (int o = 16; o; o >>= 1) s += __shfl_xor_sync(0xffffffffu, s, o);
    float inv = 1.f / s;
    float* out = g_sw + ((size_t)bn * 8 + h) * 64;
    out[lane] = e0 * inv;
    out[lane + 32] = e1 * inv;
}

// ---------------- slice_token split-K partials (no atomics) ----------------
__global__ void slicetoken_kernel()
{
    __shared__ float Ws[4][64];
    __shared__ float Fs[4][64];
    int bh = blockIdx.x;
    int chunk = blockIdx.y;
    int b = bh >> 3, h = bh & 7;
    int tid = threadIdx.x;
    int g = tid & 63;
    int cb = (tid >> 6) * 16;

    float acc[16] = {};
    float nacc = 0.f;
    size_t nbase = (size_t)b * N_ + chunk * 1024;

    for (int n4 = 0; n4 < 1024; n4 += 4) {
        int j = tid >> 6;
        int c = tid & 63;
        size_t n = nbase + n4 + j;
        Ws[j][c] = g_sw[(n * 8 + h) * 64 + c];
        Fs[j][c] = g_fx[n * 512 + h * 64 + c];
        __syncthreads();
        #pragma unroll
        for (int j2 = 0; j2 < 4; ++j2) {
            float wv = Ws[j2][g];
            if (tid < 64) nacc += wv;
            float4 f0 = *(const float4*)&Fs[j2][cb + 0];
            float4 f1 = *(const float4*)&Fs[j2][cb + 4];
            float4 f2 = *(const float4*)&Fs[j2][cb + 8];
            float4 f3 = *(const float4*)&Fs[j2][cb + 12];
            acc[0]  += wv * f0.x; acc[1]  += wv * f0.y; acc[2]  += wv * f0.z; acc[3]  += wv * f0.w;
            acc[4]  += wv * f1.x; acc[5]  += wv * f1.y; acc[6]  += wv * f1.z; acc[7]  += wv * f1.w;
            acc[8]  += wv * f2.x; acc[9]  += wv * f2.y; acc[10] += wv * f2.z; acc[11] += wv * f2.w;
            acc[12] += wv * f3.x; acc[13] += wv * f3.y; acc[14] += wv * f3.z; acc[15] += wv * f3.w;
        }
        __syncthreads();
    }
    float* p = g_part + ((size_t)chunk * 64 + bh) * 4096 + g * 64 + cb;
    #pragma unroll
    for (int q = 0; q < 16; ++q) p[q] = acc[q];
    if (tid < 64) g_npart[(chunk * 64 + bh) * 64 + tid] = nacc;
}

// ---------------- reduce partials -------------------------------------------
__global__ void reduce_token_kernel()
{
    int idx = blockIdx.x * 512 + threadIdx.x;
    float s = 0.f;
    #pragma unroll
    for (int ch = 0; ch < 16; ++ch) s += g_part[(size_t)ch * 262144 + idx];
    g_st[idx] = s;
    if (idx < 4096) {
        float ns = 0.f;
        #pragma unroll
        for (int ch = 0; ch < 16; ++ch) ns += g_npart[ch * 4096 + idx];
        g_norm[idx] = ns;
    }
}

// ---------------- normalize + QKV projections, block per (b,h) --------------
__global__ void qkv_kernel(const float* __restrict__ wq,
                           const float* __restrict__ wk,
                           const float* __restrict__ wv)
{
    __shared__ float S[64][65];
    int bh = blockIdx.x;
    int tid = threadIdx.x;
    const float* st = g_st + (size_t)bh * 4096;
    const float* nm = g_norm + bh * 64;
    for (int i = tid; i < 4096; i += 256)
        S[i >> 6][i & 63] = st[i] / (nm[i >> 6] + 1e-5f);
    __syncthreads();

    int g = tid >> 2;
    int d0 = (tid & 3) * 16;
    for (int d = d0; d < d0 + 16; ++d) {
        float q = 0.f, k = 0.f, v = 0.f;
        #pragma unroll 8
        for (int c = 0; c < 64; ++c) {
            float s = S[g][c];
            q += s * wq[d * 64 + c];
            k += s * wk[d * 64 + c];
            v += s * wv[d * 64 + c];
        }
        int o = bh * 4096 + g * 64 + d;
        g_q[o] = q; g_k[o] = k; g_v[o] = v;
    }
}

// ---------------- 64x64 attention per (b,h) ---------------------------------
__global__ void attn_kernel()
{
    __shared__ float X[64][65];
    __shared__ float Y[64][65];
    int bh = blockIdx.x;
    int tid = threadIdx.x;
    for (int i = tid; i < 4096; i += 256) {
        X[i >> 6][i & 63] = g_q[bh * 4096 + i];
        Y[i >> 6][i & 63] = g_k[bh * 4096 + i];
    }
    __syncthreads();

    int g = tid >> 2;
    int k0 = (tid & 3) * 16;
    float a[16];
    #pragma unroll
    for (int i = 0; i < 16; ++i) {
        float s = 0.f;
        for (int c = 0; c < 64; ++c) s += X[g][c] * Y[k0 + i][c];
        a[i] = s * 0.125f;
    }
    __syncthreads();
    #pragma unroll
    for (int i = 0; i < 16; ++i) X[g][k0 + i] = a[i];
    for (int i = tid; i < 4096; i += 256)
        Y[i >> 6][i & 63] = g_v[bh * 4096 + i];
    __syncthreads();

    if (tid < 64) {
        float mx = -1e30f;
        for (int k = 0; k < 64; ++k) mx = fmaxf(mx, X[tid][k]);
        float s = 0.f;
        for (int k = 0; k < 64; ++k) { float e = __expf(X[tid][k] - mx); X[tid][k] = e; s += e; }
        float inv = 1.f / s;
        for (int k = 0; k < 64; ++k) X[tid][k] *= inv;
    }
    __syncthreads();

    for (int d = k0; d < k0 + 16; ++d) {
        float o = 0.f;
        for (int k = 0; k < 64; ++k) o += X[g][k] * Y[k][d];
        g_os[bh * 4096 + g * 64 + d] = o;
    }
}

// ---------------- out_x scatter-back -----------------------------------------
__global__ void outx_kernel()
{
    __shared__ float SWt[64][68];
    __shared__ float OS[64][64];
    int ntile = blockIdx.x;
    int bh = blockIdx.y;
    int b = bh >> 3, h = bh & 7;
    int n0 = ntile * 64;
    int tid = threadIdx.x;

    #pragma unroll
    for (int i = 0; i < 4; ++i) {
        int f = tid + 256 * i;
        int n = f >> 4;
        int gg = (f & 15) * 4;
        float4 v = *(const float4*)(g_sw + ((size_t)(b * N_ + n0 + n) * 8 + h) * 64 + gg);
        SWt[gg + 0][n] = v.x;
        SWt[gg + 1][n] = v.y;
        SWt[gg + 2][n] = v.z;
        SWt[gg + 3][n] = v.w;
    }
    #pragma unroll
    for (int i = 0; i < 4; ++i) {
        int f = tid + 256 * i;
        int gg = f >> 4;
        int c4 = f & 15;
        *(float4*)&OS[gg][c4 * 4] = *(const float4*)(g_os + (size_t)bh * 4096 + gg * 64 + c4 * 4);
    }
    __syncthreads();

    int ty = tid >> 4, tx = tid & 15;
    float acc[4][4] = {};
    #pragma unroll
    for (int kk = 0; kk < 64; ++kk) {
        float4 a  = *(const float4*)&SWt[kk][ty * 4];
        float4 bv = *(const float4*)&OS[kk][tx * 4];
        acc[0][0] += a.x * bv.x; acc[0][1] += a.x * bv.y; acc[0][2] += a.x * bv.z; acc[0][3] += a.x * bv.w;
        acc[1][0] += a.y * bv.x; acc[1][1] += a.y * bv.y; acc[1][2] += a.y * bv.z; acc[1][3] += a.y * bv.w;
        acc[2][0] += a.z * bv.x; acc[2][1] += a.z * bv.y; acc[2][2] += a.z * bv.z; acc[2][3] += a.z * bv.w;
        acc[3][0] += a.w * bv.x; acc[3][1] += a.w * bv.y; acc[3][2] += a.w * bv.z; acc[3][3] += a.w * bv.w;
    }
    #pragma unroll
    for (int i = 0; i < 4; ++i) {
        int n = n0 + ty * 4 + i;
        float* o = g_ox + ((size_t)(b * N_ + n)) * 512 + h * 64 + tx * 4;
        #pragma unroll
        for (int j = 0; j < 4; ++j) o[j] = acc[i][j];
    }
}

// ---------------- final projection GEMM --------------------------------------
__global__ void final_kernel(const float* __restrict__ out_w,
                             const float* __restrict__ out_b,
                             float* __restrict__ out)
{
    __shared__ float As[32][68];
    __shared__ float Bs[32][68];
    int m0 = blockIdx.x * 64;
    int d0 = blockIdx.y * 64;
    int tid = threadIdx.x;
    int ty = tid >> 4, tx = tid & 15;
    float acc[4][4] = {};

    for (int k0 = 0; k0 < 512; k0 += 32) {
        #pragma unroll
        for (int i = 0; i < 2; ++i) {
            int f = tid + 256 * i;
            int r = f >> 3;
            int kg = f & 7;
            float4 v = *(const float4*)(g_ox + (size_t)(m0 + r) * 512 + k0 + kg * 4);
            As[kg * 4 + 0][r] = v.x;
            As[kg * 4 + 1][r] = v.y;
            As[kg * 4 + 2][r] = v.z;
            As[kg * 4 + 3][r] = v.w;
        }
        #pragma unroll
        for (int i = 0; i < 2; ++i) {
            int f = tid + 256 * i;
            int dd = f >> 3;
            int kg = f & 7;
            float4 v = *(const float4*)(out_w + (size_t)(d0 + dd) * 512 + k0 + kg * 4);
            Bs[kg * 4 + 0][dd] = v.x;
            Bs[kg * 4 + 1][dd] = v.y;
            Bs[kg * 4 + 2][dd] = v.z;
            Bs[kg * 4 + 3][dd] = v.w;
        }
        __syncthreads();
        #pragma unroll
        for (int kk = 0; kk < 32; ++kk) {
            float4 a  = *(const float4*)&As[kk][ty * 4];
            float4 bv = *(const float4*)&Bs[kk][tx * 4];
            acc[0][0] += a.x * bv.x; acc[0][1] += a.x * bv.y; acc[0][2] += a.x * bv.z; acc[0][3] += a.x * bv.w;
            acc[1][0] += a.y * bv.x; acc[1][1] += a.y * bv.y; acc[1][2] += a.y * bv.z; acc[1][3] += a.y * bv.w;
            acc[2][0] += a.z * bv.x; acc[2][1] += a.z * bv.y; acc[2][2] += a.z * bv.z; acc[2][3] += a.z * bv.w;
            acc[3][0] += a.w * bv.x; acc[3][1] += a.w * bv.y; acc[3][2] += a.w * bv.z; acc[3][3] += a.w * bv.w;
        }
        __syncthreads();
    }
    #pragma unroll
    for (int i = 0; i < 4; ++i) {
        int m = m0 + ty * 4 + i;
        float* o = out + (size_t)m * 128 + d0 + tx * 4;
        #pragma unroll
        for (int j = 0; j < 4; ++j)
            o[j] = acc[i][j] + out_b[d0 + tx * 4 + j];
    }
}

// ---------------- launch -----------------------------------------------------
extern "C" void kernel_launch(void* const* d_in, const int* in_sizes, int n_in,
                              void* d_out, int out_size)
{
    const float* x          = (const float*)d_in[0];
    const float* conv_fx_w  = (const float*)d_in[1];
    const float* conv_fx_b  = (const float*)d_in[2];
    const float* conv_x_w   = (const float*)d_in[3];
    const float* conv_x_b   = (const float*)d_in[4];
    const float* slice_w    = (const float*)d_in[5];
    const float* slice_b    = (const float*)d_in[6];
    const float* temperature= (const float*)d_in[7];
    const float* wq         = (const float*)d_in[8];
    const float* wk         = (const float*)d_in[9];
    const float* wv         = (const float*)d_in[10];
    const float* out_w      = (const float*)d_in[11];
    const float* out_b      = (const float*)d_in[12];
    float* out = (float*)d_out;

    cudaFuncSetAttribute(conv_mma_kernel,
                         cudaFuncAttributeMaxDynamicSharedMemorySize, 73728);

    wprep_kernel<<<4608, 256>>>(conv_fx_w, conv_x_w);
    conv_mma_kernel<<<dim3(1024, 8), 256, 73728>>>(x, conv_fx_b, conv_x_b);
    sliceweights_kernel<<<131072, 256>>>(slice_w, slice_b, temperature);
    slicetoken_kernel<<<dim3(64, 16), 256>>>();
    reduce_token_kernel<<<512, 512>>>();
    qkv_kernel<<<64, 256>>>(wq, wk, wv);
    attn_kernel<<<64, 256>>>();
    outx_kernel<<<dim3(256, 64), 256>>>();
    final_kernel<<<dim3(2048, 2), 256>>>(out_w, out_b, out);
}

// round 4
// speedup vs baseline: 6.0113x; 4.4642x over previous
#include <cuda_runtime.h>

#define B_     8
#define N_     16384
#define DIM_   128
#define HEADS_ 8
#define DH_    64
#define INNER_ 512
#define G_     64

// ---------------- scratch (device globals; no runtime allocation) ----------
__device__ float g_fx[67108864];   // (B,N,512)  conv_fx output
__device__ float g_xm[67108864];   // (B,N,512)  conv_x  output
__device__ float g_sw[67108864];   // (B,N,H,64) slice weights
__device__ float g_ox[67108864];   // (B,N,512)  out_x
__device__ float g_part[4194304];
__device__ float g_npart[65536];
__device__ float g_st[262144];
__device__ float g_norm[4096];
__device__ float g_q[262144];
__device__ float g_k[262144];
__device__ float g_v[262144];
__device__ float g_os[262144];
__device__ float g_wt[1179648];    // transposed tf32-rounded weights [1024 co][1152 k]

__device__ __forceinline__ unsigned cvt_tf32(float f) {
    unsigned u;
    asm("cvt.rna.tf32.f32 %0, %1;" : "=r"(u) : "f"(f));
    return u;
}
__device__ __forceinline__ unsigned smem_u32(const void* p) {
    unsigned a;
    asm("{ .reg .u64 t; cvta.to.shared.u64 t, %1; cvt.u32.u64 %0, t; }"
        : "=r"(a) : "l"(p));
    return a;
}
__device__ __forceinline__ void mma_tf32(float* c, const unsigned* a, const unsigned* b) {
    asm volatile("mma.sync.aligned.m16n8k8.row.col.f32.tf32.tf32.f32 "
                 "{%0,%1,%2,%3}, {%4,%5,%6,%7}, {%8,%9}, {%0,%1,%2,%3};"
                 : "+f"(c[0]), "+f"(c[1]), "+f"(c[2]), "+f"(c[3])
                 : "r"(a[0]), "r"(a[1]), "r"(a[2]), "r"(a[3]),
                   "r"(b[0]), "r"(b[1]));
}

// ---------------- weight transpose + tf32 rounding --------------------------
__global__ void wprep_kernel(const float* __restrict__ wfx,
                             const float* __restrict__ wx)
{
    int idx = blockIdx.x * 256 + threadIdx.x;          // < 1024*1152
    if (idx >= 1179648) return;
    int co = idx / 1152;
    int k  = idx - co * 1152;
    const float* w = (co < 512) ? wfx : wx;
    int c = (co < 512) ? co : co - 512;
    float v = w[(size_t)k * 512 + c];
    g_wt[idx] = __uint_as_float(cvt_tf32(v));
}

// ---------------- conv via tf32 mma.sync ------------------------------------
__global__ void __launch_bounds__(256, 2)
conv_mma_kernel(const float* __restrict__ x,
                const float* __restrict__ bfx, const float* __restrict__ bx)
{
    extern __shared__ float sm[];
    const int tid  = threadIdx.x;
    const int wid  = tid >> 5;
    const int lane = tid & 31;
    const int g    = lane >> 2;
    const int t4   = lane & 3;
    const int warpM = wid & 1;
    const int warpN = wid >> 1;

    const int row = blockIdx.x;          // b*128 + y
    const int b   = row >> 7;
    const int y   = row & 127;
    const int ct  = blockIdx.y;          // 0..7 (0-3 fx, 4-7 xm)
    const int co0 = ct * 128;

    const float* xrowbase = x + (size_t)b * (N_ * DIM_);

    float acc[4][4][4] = {};
    uint4 av[4];

    auto prefetchA = [&](int c) {
        const int tap = c >> 2;
        const int dy = tap / 3 - 1, dx = tap % 3 - 1;
        const int yy = y + dy;
        const bool rowok = (unsigned)yy < 128u;
        const int ci0 = (c & 3) * 32;
        #pragma unroll
        for (int i = 0; i < 4; ++i) {
            int f = tid + 256 * i;
            int r = f >> 3, q = f & 7;
            int xp = r + dx;
            uint4 v = make_uint4(0u, 0u, 0u, 0u);
            if (rowok && (unsigned)xp < 128u) {
                float4 fv = *(const float4*)(xrowbase + ((size_t)yy * 128 + xp) * 128
                                             + ci0 + q * 4);
                v.x = cvt_tf32(fv.x); v.y = cvt_tf32(fv.y);
                v.z = cvt_tf32(fv.z); v.w = cvt_tf32(fv.w);
            }
            av[i] = v;
        }
    };
    auto storeA = [&](int s) {
        float* As_ = sm + s * 9216;
        #pragma unroll
        for (int i = 0; i < 4; ++i) {
            int f = tid + 256 * i;
            int r = f >> 3, q = f & 7;
            *(uint4*)(As_ + r * 36 + q * 4) = av[i];
        }
    };
    auto cpasyncB = [&](int c, int s) {
        float* Bs_ = sm + s * 9216 + 4608;
        const int k0w = (c >> 2) * 128 + (c & 3) * 32;
        #pragma unroll
        for (int i = 0; i < 4; ++i) {
            int f = tid + 256 * i;
            int r = f >> 3, q = f & 7;
            const float* src = g_wt + (size_t)(co0 + r) * 1152 + k0w + q * 4;
            unsigned dst = smem_u32(Bs_ + r * 36 + q * 4);
            asm volatile("cp.async.cg.shared.global [%0], [%1], 16;"
                         :: "r"(dst), "l"(src));
        }
    };
    auto compute = [&](int s) {
        const float* As_ = sm + s * 9216;
        const float* Bs_ = As_ + 4608;
        const int m0 = warpM * 64;
        const int n0 = warpN * 32;
        #pragma unroll
        for (int ks = 0; ks < 4; ++ks) {
            const int kk = ks * 8;
            unsigned af[4][4];
            #pragma unroll
            for (int mt = 0; mt < 4; ++mt) {
                const float* p0 = As_ + (m0 + mt * 16 + g) * 36 + kk + t4;
                const float* p1 = p0 + 8 * 36;
                af[mt][0] = __float_as_uint(p0[0]);
                af[mt][1] = __float_as_uint(p1[0]);
                af[mt][2] = __float_as_uint(p0[4]);
                af[mt][3] = __float_as_uint(p1[4]);
            }
            unsigned bf[4][2];
            #pragma unroll
            for (int nt = 0; nt < 4; ++nt) {
                const float* p = Bs_ + (n0 + nt * 8 + g) * 36 + kk + t4;
                bf[nt][0] = __float_as_uint(p[0]);
                bf[nt][1] = __float_as_uint(p[4]);
            }
            #pragma unroll
            for (int mt = 0; mt < 4; ++mt)
                #pragma unroll
                for (int nt = 0; nt < 4; ++nt)
                    mma_tf32(acc[mt][nt], af[mt], bf[nt]);
        }
    };

    prefetchA(0);
    storeA(0);
    cpasyncB(0, 0);
    asm volatile("cp.async.commit_group;");
    prefetchA(1);
    asm volatile("cp.async.wait_group 0;");
    __syncthreads();

    for (int c = 0; c < 36; ++c) {
        const int s = c & 1;
        if (c < 35) {
            storeA(s ^ 1);
            cpasyncB(c + 1, s ^ 1);
            asm volatile("cp.async.commit_group;");
        }
        if (c < 34) prefetchA(c + 2);
        compute(s);
        if (c < 35) {
            asm volatile("cp.async.wait_group 0;");
            __syncthreads();
        }
    }

    float* outp = (ct < 4) ? g_fx : g_xm;
    const float* biasp = ((ct < 4) ? bfx : bx) + (ct & 3) * 128;
    const size_t rowbase = (size_t)row * 128 * 512 + (ct & 3) * 128;

    #pragma unroll
    for (int mt = 0; mt < 4; ++mt) {
        const int m = warpM * 64 + mt * 16 + g;
        #pragma unroll
        for (int nt = 0; nt < 4; ++nt) {
            const int nl = warpN * 32 + nt * 8 + t4 * 2;
            float b0 = __ldg(biasp + nl), b1 = __ldg(biasp + nl + 1);
            float2 v0 = make_float2(acc[mt][nt][0] + b0, acc[mt][nt][1] + b1);
            float2 v1 = make_float2(acc[mt][nt][2] + b0, acc[mt][nt][3] + b1);
            *(float2*)(outp + rowbase + (size_t)m * 512 + nl) = v0;
            *(float2*)(outp + rowbase + (size_t)(m + 8) * 512 + nl) = v1;
        }
    }
}

// ---------------- slice weights: tiled GEMM + fused softmax -----------------
// grid (2048 token-tiles of 64, 8 heads), 256 threads.
// Thread: 2 tok x 8 g. Softmax over G via shfl among the 8 lanes of a token.
__global__ void __launch_bounds__(256, 4)
sliceweights_kernel(const float* __restrict__ slice_w,
                    const float* __restrict__ slice_b,
                    const float* __restrict__ temperature)
{
    __shared__ float Xst[64][68];   // [c][tok]
    __shared__ float Wt[64][68];    // [c][g]
    const int tid = threadIdx.x;
    const int h   = blockIdx.y;
    const int bn0 = blockIdx.x * 64;

    // load slice_w transposed: Wt[c][g] = slice_w[g*64+c]
    #pragma unroll
    for (int i = tid; i < 4096; i += 256) {
        int g = i >> 6, c = i & 63;
        Wt[c][g] = slice_w[i];
    }
    // load x_mid slice transposed: Xst[c][t]
    #pragma unroll
    for (int i = tid; i < 4096; i += 256) {
        int t = i >> 6, c = i & 63;
        Xst[c][t] = g_xm[(size_t)(bn0 + t) * 512 + h * 64 + c];
    }
    __syncthreads();

    const int tx = tid & 7;          // g-group (8 g's)
    const int ty = tid >> 3;         // token-group (2 tokens)
    const int t0 = ty * 2;
    const int g0 = tx * 8;

    float acc[2][8] = {};
    #pragma unroll
    for (int c = 0; c < 64; ++c) {
        float2 a  = *(const float2*)&Xst[c][t0];
        float4 b0 = *(const float4*)&Wt[c][g0];
        float4 b1 = *(const float4*)&Wt[c][g0 + 4];
        acc[0][0] += a.x * b0.x; acc[0][1] += a.x * b0.y;
        acc[0][2] += a.x * b0.z; acc[0][3] += a.x * b0.w;
        acc[0][4] += a.x * b1.x; acc[0][5] += a.x * b1.y;
        acc[0][6] += a.x * b1.z; acc[0][7] += a.x * b1.w;
        acc[1][0] += a.y * b0.x; acc[1][1] += a.y * b0.y;
        acc[1][2] += a.y * b0.z; acc[1][3] += a.y * b0.w;
        acc[1][4] += a.y * b1.x; acc[1][5] += a.y * b1.y;
        acc[1][6] += a.y * b1.z; acc[1][7] += a.y * b1.w;
    }

    float tv = temperature[h];
    tv = fminf(fmaxf(tv, 0.1f), 5.0f);
    float invt = 1.f / tv;
    float bias[8];
    #pragma unroll
    for (int j = 0; j < 8; ++j) bias[j] = __ldg(slice_b + g0 + j);

    #pragma unroll
    for (int i = 0; i < 2; ++i) {
        float l[8];
        #pragma unroll
        for (int j = 0; j < 8; ++j) l[j] = (acc[i][j] + bias[j]) * invt;
        float mx = l[0];
        #pragma unroll
        for (int j = 1; j < 8; ++j) mx = fmaxf(mx, l[j]);
        #pragma unroll
        for (int o = 1; o < 8; o <<= 1)
            mx = fmaxf(mx, __shfl_xor_sync(0xffffffffu, mx, o));
        float s = 0.f;
        #pragma unroll
        for (int j = 0; j < 8; ++j) { l[j] = __expf(l[j] - mx); s += l[j]; }
        #pragma unroll
        for (int o = 1; o < 8; o <<= 1)
            s += __shfl_xor_sync(0xffffffffu, s, o);
        float inv = 1.f / s;
        float* outp = g_sw + ((size_t)(bn0 + t0 + i) * 8 + h) * 64 + g0;
        float4 v0 = make_float4(l[0] * inv, l[1] * inv, l[2] * inv, l[3] * inv);
        float4 v1 = make_float4(l[4] * inv, l[5] * inv, l[6] * inv, l[7] * inv);
        *(float4*)outp = v0;
        *(float4*)(outp + 4) = v1;
    }
}

// ---------------- slice_token split-K partials (no atomics) ----------------
__global__ void slicetoken_kernel()
{
    __shared__ float Ws[4][64];
    __shared__ float Fs[4][64];
    int bh = blockIdx.x;
    int chunk = blockIdx.y;
    int b = bh >> 3, h = bh & 7;
    int tid = threadIdx.x;
    int g = tid & 63;
    int cb = (tid >> 6) * 16;

    float acc[16] = {};
    float nacc = 0.f;
    size_t nbase = (size_t)b * N_ + chunk * 1024;

    for (int n4 = 0; n4 < 1024; n4 += 4) {
        int j = tid >> 6;
        int c = tid & 63;
        size_t n = nbase + n4 + j;
        Ws[j][c] = g_sw[(n * 8 + h) * 64 + c];
        Fs[j][c] = g_fx[n * 512 + h * 64 + c];
        __syncthreads();
        #pragma unroll
        for (int j2 = 0; j2 < 4; ++j2) {
            float wv = Ws[j2][g];
            if (tid < 64) nacc += wv;
            float4 f0 = *(const float4*)&Fs[j2][cb + 0];
            float4 f1 = *(const float4*)&Fs[j2][cb + 4];
            float4 f2 = *(const float4*)&Fs[j2][cb + 8];
            float4 f3 = *(const float4*)&Fs[j2][cb + 12];
            acc[0]  += wv * f0.x; acc[1]  += wv * f0.y; acc[2]  += wv * f0.z; acc[3]  += wv * f0.w;
            acc[4]  += wv * f1.x; acc[5]  += wv * f1.y; acc[6]  += wv * f1.z; acc[7]  += wv * f1.w;
            acc[8]  += wv * f2.x; acc[9]  += wv * f2.y; acc[10] += wv * f2.z; acc[11] += wv * f2.w;
            acc[12] += wv * f3.x; acc[13] += wv * f3.y; acc[14] += wv * f3.z; acc[15] += wv * f3.w;
        }
        __syncthreads();
    }
    float* p = g_part + ((size_t)chunk * 64 + bh) * 4096 + g * 64 + cb;
    #pragma unroll
    for (int q = 0; q < 16; ++q) p[q] = acc[q];
    if (tid < 64) g_npart[(chunk * 64 + bh) * 64 + tid] = nacc;
}

// ---------------- reduce partials -------------------------------------------
__global__ void reduce_token_kernel()
{
    int idx = blockIdx.x * 512 + threadIdx.x;
    float s = 0.f;
    #pragma unroll
    for (int ch = 0; ch < 16; ++ch) s += g_part[(size_t)ch * 262144 + idx];
    g_st[idx] = s;
    if (idx < 4096) {
        float ns = 0.f;
        #pragma unroll
        for (int ch = 0; ch < 16; ++ch) ns += g_npart[ch * 4096 + idx];
        g_norm[idx] = ns;
    }
}

// ---------------- normalize + QKV projections, block per (b,h) --------------
__global__ void qkv_kernel(const float* __restrict__ wq,
                           const float* __restrict__ wk,
                           const float* __restrict__ wv)
{
    __shared__ float S[64][65];
    int bh = blockIdx.x;
    int tid = threadIdx.x;
    const float* st = g_st + (size_t)bh * 4096;
    const float* nm = g_norm + bh * 64;
    for (int i = tid; i < 4096; i += 256)
        S[i >> 6][i & 63] = st[i] / (nm[i >> 6] + 1e-5f);
    __syncthreads();

    int g = tid >> 2;
    int d0 = (tid & 3) * 16;
    for (int d = d0; d < d0 + 16; ++d) {
        float q = 0.f, k = 0.f, v = 0.f;
        #pragma unroll 8
        for (int c = 0; c < 64; ++c) {
            float s = S[g][c];
            q += s * wq[d * 64 + c];
            k += s * wk[d * 64 + c];
            v += s * wv[d * 64 + c];
        }
        int o = bh * 4096 + g * 64 + d;
        g_q[o] = q; g_k[o] = k; g_v[o] = v;
    }
}

// ---------------- 64x64 attention per (b,h) ---------------------------------
__global__ void attn_kernel()
{
    __shared__ float X[64][65];
    __shared__ float Y[64][65];
    int bh = blockIdx.x;
    int tid = threadIdx.x;
    for (int i = tid; i < 4096; i += 256) {
        X[i >> 6][i & 63] = g_q[bh * 4096 + i];
        Y[i >> 6][i & 63] = g_k[bh * 4096 + i];
    }
    __syncthreads();

    int g = tid >> 2;
    int k0 = (tid & 3) * 16;
    float a[16];
    #pragma unroll
    for (int i = 0; i < 16; ++i) {
        float s = 0.f;
        for (int c = 0; c < 64; ++c) s += X[g][c] * Y[k0 + i][c];
        a[i] = s * 0.125f;
    }
    __syncthreads();
    #pragma unroll
    for (int i = 0; i < 16; ++i) X[g][k0 + i] = a[i];
    for (int i = tid; i < 4096; i += 256)
        Y[i >> 6][i & 63] = g_v[bh * 4096 + i];
    __syncthreads();

    if (tid < 64) {
        float mx = -1e30f;
        for (int k = 0; k < 64; ++k) mx = fmaxf(mx, X[tid][k]);
        float s = 0.f;
        for (int k = 0; k < 64; ++k) { float e = __expf(X[tid][k] - mx); X[tid][k] = e; s += e; }
        float inv = 1.f / s;
        for (int k = 0; k < 64; ++k) X[tid][k] *= inv;
    }
    __syncthreads();

    for (int d = k0; d < k0 + 16; ++d) {
        float o = 0.f;
        for (int k = 0; k < 64; ++k) o += X[g][k] * Y[k][d];
        g_os[bh * 4096 + g * 64 + d] = o;
    }
}

// ---------------- out_x scatter-back -----------------------------------------
__global__ void outx_kernel()
{
    __shared__ float SWt[64][68];
    __shared__ float OS[64][64];
    int ntile = blockIdx.x;
    int bh = blockIdx.y;
    int b = bh >> 3, h = bh & 7;
    int n0 = ntile * 64;
    int tid = threadIdx.x;

    #pragma unroll
    for (int i = 0; i < 4; ++i) {
        int f = tid + 256 * i;
        int n = f >> 4;
        int gg = (f & 15) * 4;
        float4 v = *(const float4*)(g_sw + ((size_t)(b * N_ + n0 + n) * 8 + h) * 64 + gg);
        SWt[gg + 0][n] = v.x;
        SWt[gg + 1][n] = v.y;
        SWt[gg + 2][n] = v.z;
        SWt[gg + 3][n] = v.w;
    }
    #pragma unroll
    for (int i = 0; i < 4; ++i) {
        int f = tid + 256 * i;
        int gg = f >> 4;
        int c4 = f & 15;
        *(float4*)&OS[gg][c4 * 4] = *(const float4*)(g_os + (size_t)bh * 4096 + gg * 64 + c4 * 4);
    }
    __syncthreads();

    int ty = tid >> 4, tx = tid & 15;
    float acc[4][4] = {};
    #pragma unroll
    for (int kk = 0; kk < 64; ++kk) {
        float4 a  = *(const float4*)&SWt[kk][ty * 4];
        float4 bv = *(const float4*)&OS[kk][tx * 4];
        acc[0][0] += a.x * bv.x; acc[0][1] += a.x * bv.y; acc[0][2] += a.x * bv.z; acc[0][3] += a.x * bv.w;
        acc[1][0] += a.y * bv.x; acc[1][1] += a.y * bv.y; acc[1][2] += a.y * bv.z; acc[1][3] += a.y * bv.w;
        acc[2][0] += a.z * bv.x; acc[2][1] += a.z * bv.y; acc[2][2] += a.z * bv.z; acc[2][3] += a.z * bv.w;
        acc[3][0] += a.w * bv.x; acc[3][1] += a.w * bv.y; acc[3][2] += a.w * bv.z; acc[3][3] += a.w * bv.w;
    }
    #pragma unroll
    for (int i = 0; i < 4; ++i) {
        int n = n0 + ty * 4 + i;
        float* o = g_ox + ((size_t)(b * N_ + n)) * 512 + h * 64 + tx * 4;
        #pragma unroll
        for (int j = 0; j < 4; ++j) o[j] = acc[i][j];
    }
}

// ---------------- final projection GEMM --------------------------------------
__global__ void final_kernel(const float* __restrict__ out_w,
                             const float* __restrict__ out_b,
                             float* __restrict__ out)
{
    __shared__ float As[32][68];
    __shared__ float Bs[32][68];
    int m0 = blockIdx.x * 64;
    int d0 = blockIdx.y * 64;
    int tid = threadIdx.x;
    int ty = tid >> 4, tx = tid & 15;
    float acc[4][4] = {};

    for (int k0 = 0; k0 < 512; k0 += 32) {
        #pragma unroll
        for (int i = 0; i < 2; ++i) {
            int f = tid + 256 * i;
            int r = f >> 3;
            int kg = f & 7;
            float4 v = *(const float4*)(g_ox + (size_t)(m0 + r) * 512 + k0 + kg * 4);
            As[kg * 4 + 0][r] = v.x;
            As[kg * 4 + 1][r] = v.y;
            As[kg * 4 + 2][r] = v.z;
            As[kg * 4 + 3][r] = v.w;
        }
        #pragma unroll
        for (int i = 0; i < 2; ++i) {
            int f = tid + 256 * i;
            int dd = f >> 3;
            int kg = f & 7;
            float4 v = *(const float4*)(out_w + (size_t)(d0 + dd) * 512 + k0 + kg * 4);
            Bs[kg * 4 + 0][dd] = v.x;
            Bs[kg * 4 + 1][dd] = v.y;
            Bs[kg * 4 + 2][dd] = v.z;
            Bs[kg * 4 + 3][dd] = v.w;
        }
        __syncthreads();
        #pragma unroll
        for (int kk = 0; kk < 32; ++kk) {
            float4 a  = *(const float4*)&As[kk][ty * 4];
            float4 bv = *(const float4*)&Bs[kk][tx * 4];
            acc[0][0] += a.x * bv.x; acc[0][1] += a.x * bv.y; acc[0][2] += a.x * bv.z; acc[0][3] += a.x * bv.w;
            acc[1][0] += a.y * bv.x; acc[1][1] += a.y * bv.y; acc[1][2] += a.y * bv.z; acc[1][3] += a.y * bv.w;
            acc[2][0] += a.z * bv.x; acc[2][1] += a.z * bv.y; acc[2][2] += a.z * bv.z; acc[2][3] += a.z * bv.w;
            acc[3][0] += a.w * bv.x; acc[3][1] += a.w * bv.y; acc[3][2] += a.w * bv.z; acc[3][3] += a.w * bv.w;
        }
        __syncthreads();
    }
    #pragma unroll
    for (int i = 0; i < 4; ++i) {
        int m = m0 + ty * 4 + i;
        float* o = out + (size_t)m * 128 + d0 + tx * 4;
        #pragma unroll
        for (int j = 0; j < 4; ++j)
            o[j] = acc[i][j] + out_b[d0 + tx * 4 + j];
    }
}

// ---------------- launch -----------------------------------------------------
extern "C" void kernel_launch(void* const* d_in, const int* in_sizes, int n_in,
                              void* d_out, int out_size)
{
    const float* x          = (const float*)d_in[0];
    const float* conv_fx_w  = (const float*)d_in[1];
    const float* conv_fx_b  = (const float*)d_in[2];
    const float* conv_x_w   = (const float*)d_in[3];
    const float* conv_x_b   = (const float*)d_in[4];
    const float* slice_w    = (const float*)d_in[5];
    const float* slice_b    = (const float*)d_in[6];
    const float* temperature= (const float*)d_in[7];
    const float* wq         = (const float*)d_in[8];
    const float* wk         = (const float*)d_in[9];
    const float* wv         = (const float*)d_in[10];
    const float* out_w      = (const float*)d_in[11];
    const float* out_b      = (const float*)d_in[12];
    float* out = (float*)d_out;

    cudaFuncSetAttribute(conv_mma_kernel,
                         cudaFuncAttributeMaxDynamicSharedMemorySize, 73728);

    wprep_kernel<<<4608, 256>>>(conv_fx_w, conv_x_w);
    conv_mma_kernel<<<dim3(1024, 8), 256, 73728>>>(x, conv_fx_b, conv_x_b);
    sliceweights_kernel<<<dim3(2048, 8), 256>>>(slice_w, slice_b, temperature);
    slicetoken_kernel<<<dim3(64, 16), 256>>>();
    reduce_token_kernel<<<512, 512>>>();
    qkv_kernel<<<64, 256>>>(wq, wk, wv);
    attn_kernel<<<64, 256>>>();
    outx_kernel<<<dim3(256, 64), 256>>>();
    final_kernel<<<dim3(2048, 2), 256>>>(out_w, out_b, out);
}

// round 5
// speedup vs baseline: 6.3742x; 1.0604x over previous
#include <cuda_runtime.h>

#define B_     8
#define N_     16384
#define DIM_   128

// ---------------- scratch (device globals) ----------------------------------
__device__ float g_xr[16777216];   // tf32-rounded x (B,N,128)
__device__ float g_fxt[67108864];  // conv_fx output TRANSPOSED (B,512co,16384n)
__device__ float g_xm[67108864];   // conv_x output (B,N,512)
__device__ float g_swt[67108864];  // slice weights TRANSPOSED (B,H,64g,16384n)
__device__ float g_ox[67108864];   // out_x (B,N,512)
__device__ float g_part[4194304];  // 16 chunks x 64 bh x 4096
__device__ float g_npart[1048576]; // 64 bh x 256 tiles x 64 g
__device__ float g_st[262144];
__device__ float g_norm[4096];
__device__ float g_q[262144];
__device__ float g_k[262144];
__device__ float g_v[262144];
__device__ float g_os[262144];
__device__ float g_wt[1179648];    // tf32 weights [1024 co][1152 k]

__device__ __forceinline__ unsigned cvt_tf32(float f) {
    unsigned u;
    asm("cvt.rna.tf32.f32 %0, %1;" : "=r"(u) : "f"(f));
    return u;
}
__device__ __forceinline__ unsigned smem_u32(const void* p) {
    unsigned a;
    asm("{ .reg .u64 t; cvta.to.shared.u64 t, %1; cvt.u32.u64 %0, t; }"
        : "=r"(a) : "l"(p));
    return a;
}
__device__ __forceinline__ void mma_tf32(float* c, const unsigned* a, const unsigned* b) {
    asm volatile("mma.sync.aligned.m16n8k8.row.col.f32.tf32.tf32.f32 "
                 "{%0,%1,%2,%3}, {%4,%5,%6,%7}, {%8,%9}, {%0,%1,%2,%3};"
                 : "+f"(c[0]), "+f"(c[1]), "+f"(c[2]), "+f"(c[3])
                 : "r"(a[0]), "r"(a[1]), "r"(a[2]), "r"(a[3]),
                   "r"(b[0]), "r"(b[1]));
}
#define CP16(dst, src) \
    asm volatile("cp.async.cg.shared.global [%0], [%1], 16;" :: "r"(dst), "l"(src))
#define CP16Z(dst, src, sz) \
    asm volatile("cp.async.cg.shared.global [%0], [%1], 16, %2;" :: "r"(dst), "l"(src), "r"(sz))
#define CP_COMMIT() asm volatile("cp.async.commit_group;")
#define CP_WAIT(n)  asm volatile("cp.async.wait_group %0;" :: "n"(n))

// ---------------- prep: weights + x tf32 rounding ---------------------------
__global__ void wprep_kernel(const float* __restrict__ wfx,
                             const float* __restrict__ wx)
{
    int idx = blockIdx.x * 256 + threadIdx.x;
    if (idx >= 1179648) return;
    int co = idx / 1152;
    int k  = idx - co * 1152;
    const float* w = (co < 512) ? wfx : wx;
    int c = (co < 512) ? co : co - 512;
    g_wt[idx] = __uint_as_float(cvt_tf32(w[(size_t)k * 512 + c]));
}
__global__ void wprep_x_kernel(const float* __restrict__ x)
{
    int idx = (blockIdx.x * 256 + threadIdx.x) * 4;
    float4 v = *(const float4*)(x + idx);
    uint4 u;
    u.x = cvt_tf32(v.x); u.y = cvt_tf32(v.y);
    u.z = cvt_tf32(v.z); u.w = cvt_tf32(v.w);
    *(uint4*)(g_xr + idx) = u;
}

// ---------------- conv: implicit GEMM, tf32 mma, full cp.async pipeline -----
// grid (1024 rows, 4 ctiles of 256co), 256 threads, warp tile 64x64.
// Stage = A 128x36f (18KB) + B 256x36f (36KB); 3 stages (162KB), 1 CTA/SM.
__global__ void __launch_bounds__(256)
conv_mma_kernel(const float* __restrict__ bfx, const float* __restrict__ bx)
{
    extern __shared__ float sm[];
    const int tid  = threadIdx.x;
    const int wid  = tid >> 5;
    const int lane = tid & 31;
    const int g    = lane >> 2;
    const int t4   = lane & 3;
    const int warpM = wid & 1;
    const int warpN = wid >> 1;

    const int row = blockIdx.x;
    const int b   = row >> 7;
    const int y   = row & 127;
    const int ct  = blockIdx.y;          // 0..3
    const int co0 = ct * 256;

    float acc[4][8][4] = {};

    auto load_stage = [&](int c, int s) {
        float* base = sm + s * 13824;
        const int tap = c >> 2;
        const int dy = tap / 3 - 1, dx = tap % 3 - 1;
        const int yy = y + dy;
        const bool rowok = (unsigned)yy < 128u;
        const int ci0 = (c & 3) * 32;
        const int k0w = tap * 128 + ci0;
        const float* xb = g_xr + ((size_t)(b * 128 + (rowok ? yy : 0)) * 128) * 128;
        #pragma unroll
        for (int i = 0; i < 4; ++i) {
            int f = tid + 256 * i;
            int r = f >> 3, q = f & 7;
            int xp = r + dx;
            bool ok = rowok && (unsigned)xp < 128u;
            const float* src = xb + (size_t)(ok ? xp : 0) * 128 + ci0 + q * 4;
            CP16Z(smem_u32(base + r * 36 + q * 4), src, ok ? 16 : 0);
        }
        #pragma unroll
        for (int i = 0; i < 8; ++i) {
            int f = tid + 256 * i;
            int r = f >> 3, q = f & 7;
            const float* src = g_wt + (size_t)(co0 + r) * 1152 + k0w + q * 4;
            CP16(smem_u32(base + 4608 + r * 36 + q * 4), src);
        }
    };
    auto compute = [&](int s) {
        const float* As_ = sm + s * 13824;
        const float* Bs_ = As_ + 4608;
        const int m0 = warpM * 64;
        const int n0 = warpN * 64;
        #pragma unroll
        for (int ks = 0; ks < 4; ++ks) {
            const int kk = ks * 8;
            unsigned af[4][4];
            #pragma unroll
            for (int mt = 0; mt < 4; ++mt) {
                const float* p0 = As_ + (m0 + mt * 16 + g) * 36 + kk + t4;
                const float* p1 = p0 + 288;
                af[mt][0] = __float_as_uint(p0[0]);
                af[mt][1] = __float_as_uint(p1[0]);
                af[mt][2] = __float_as_uint(p0[4]);
                af[mt][3] = __float_as_uint(p1[4]);
            }
            unsigned bf[8][2];
            #pragma unroll
            for (int nt = 0; nt < 8; ++nt) {
                const float* p = Bs_ + (n0 + nt * 8 + g) * 36 + kk + t4;
                bf[nt][0] = __float_as_uint(p[0]);
                bf[nt][1] = __float_as_uint(p[4]);
            }
            #pragma unroll
            for (int mt = 0; mt < 4; ++mt)
                #pragma unroll
                for (int nt = 0; nt < 8; ++nt)
                    mma_tf32(acc[mt][nt], af[mt], bf[nt]);
        }
    };

    load_stage(0, 0); CP_COMMIT();
    load_stage(1, 1); CP_COMMIT();

    for (int c = 0; c < 36; ++c) {
        const int s = c % 3;
        if (c + 2 < 36) {
            load_stage(c + 2, (c + 2) % 3);
            CP_COMMIT();
            CP_WAIT(1);
        } else {
            CP_WAIT(0);
        }
        __syncthreads();
        compute(s);
        __syncthreads();
    }

    // epilogue
    if (ct < 2) {   // fx: transposed write (B,512co,16384n)
        const float* biasp = bfx + ct * 256;
        float* outb = g_fxt + ((size_t)b * 512 + ct * 256) * 16384 + y * 128;
        #pragma unroll
        for (int mt = 0; mt < 4; ++mt) {
            const int m = warpM * 64 + mt * 16 + g;
            #pragma unroll
            for (int nt = 0; nt < 8; ++nt) {
                const int nl = warpN * 64 + nt * 8 + t4 * 2;
                #pragma unroll
                for (int j = 0; j < 2; ++j) {
                    float bb = __ldg(biasp + nl + j);
                    float* col = outb + (size_t)(nl + j) * 16384;
                    col[m]     = acc[mt][nt][j]     + bb;
                    col[m + 8] = acc[mt][nt][2 + j] + bb;
                }
            }
        }
    } else {        // xm: normal layout (B,N,512)
        const float* biasp = bx + (ct - 2) * 256;
        float* outb = g_xm + ((size_t)(b * N_ + y * 128)) * 512 + (ct - 2) * 256;
        #pragma unroll
        for (int mt = 0; mt < 4; ++mt) {
            const int m = warpM * 64 + mt * 16 + g;
            #pragma unroll
            for (int nt = 0; nt < 8; ++nt) {
                const int nl = warpN * 64 + nt * 8 + t4 * 2;
                float b0 = __ldg(biasp + nl), b1 = __ldg(biasp + nl + 1);
                *(float2*)(outb + (size_t)m * 512 + nl) =
                    make_float2(acc[mt][nt][0] + b0, acc[mt][nt][1] + b1);
                *(float2*)(outb + (size_t)(m + 8) * 512 + nl) =
                    make_float2(acc[mt][nt][2] + b0, acc[mt][nt][3] + b1);
            }
        }
    }
}

// ---------------- slice weights: GEMM + softmax, transposed out + norm ------
// grid (2048 token-tiles of 64, 8 heads), 256 threads; thread = 2 tok x 8 g.
__global__ void __launch_bounds__(256, 4)
sliceweights_kernel(const float* __restrict__ slice_w,
                    const float* __restrict__ slice_b,
                    const float* __restrict__ temperature)
{
    __shared__ float Xst[64][68];
    __shared__ float Wt[64][68];
    __shared__ float NP[8][64];
    const int tid = threadIdx.x;
    const int h   = blockIdx.y;
    const int bn0 = blockIdx.x * 64;
    const int b   = bn0 >> 14;
    const int nin = bn0 & 16383;

    for (int i = tid; i < 4096; i += 256) {
        int gg = i >> 6, c = i & 63;
        Wt[c][gg] = slice_w[i];
    }
    for (int i = tid; i < 4096; i += 256) {
        int t = i >> 6, c = i & 63;
        Xst[c][t] = g_xm[(size_t)(bn0 + t) * 512 + h * 64 + c];
    }
    __syncthreads();

    const int tx = tid & 7;
    const int ty = tid >> 3;
    const int t0 = ty * 2;
    const int g0 = tx * 8;
    const int lane = tid & 31;

    float acc[2][8] = {};
    #pragma unroll
    for (int c = 0; c < 64; ++c) {
        float2 a  = *(const float2*)&Xst[c][t0];
        float4 b0 = *(const float4*)&Wt[c][g0];
        float4 b1 = *(const float4*)&Wt[c][g0 + 4];
        acc[0][0] += a.x * b0.x; acc[0][1] += a.x * b0.y;
        acc[0][2] += a.x * b0.z; acc[0][3] += a.x * b0.w;
        acc[0][4] += a.x * b1.x; acc[0][5] += a.x * b1.y;
        acc[0][6] += a.x * b1.z; acc[0][7] += a.x * b1.w;
        acc[1][0] += a.y * b0.x; acc[1][1] += a.y * b0.y;
        acc[1][2] += a.y * b0.z; acc[1][3] += a.y * b0.w;
        acc[1][4] += a.y * b1.x; acc[1][5] += a.y * b1.y;
        acc[1][6] += a.y * b1.z; acc[1][7] += a.y * b1.w;
    }

    float tv = temperature[h];
    tv = fminf(fmaxf(tv, 0.1f), 5.0f);
    float invt = 1.f / tv;
    float bias[8];
    #pragma unroll
    for (int j = 0; j < 8; ++j) bias[j] = __ldg(slice_b + g0 + j);

    float w0[8], w1[8];
    #pragma unroll
    for (int i = 0; i < 2; ++i) {
        float l[8];
        #pragma unroll
        for (int j = 0; j < 8; ++j) l[j] = (acc[i][j] + bias[j]) * invt;
        float mx = l[0];
        #pragma unroll
        for (int j = 1; j < 8; ++j) mx = fmaxf(mx, l[j]);
        #pragma unroll
        for (int o = 1; o < 8; o <<= 1)
            mx = fmaxf(mx, __shfl_xor_sync(0xffffffffu, mx, o));
        float s = 0.f;
        #pragma unroll
        for (int j = 0; j < 8; ++j) { l[j] = __expf(l[j] - mx); s += l[j]; }
        #pragma unroll
        for (int o = 1; o < 8; o <<= 1)
            s += __shfl_xor_sync(0xffffffffu, s, o);
        float inv = 1.f / s;
        #pragma unroll
        for (int j = 0; j < 8; ++j) {
            float v = l[j] * inv;
            if (i == 0) w0[j] = v; else w1[j] = v;
        }
    }

    // transposed global write: g_swt[(b*8+h)*64+g][n]
    float* gb = g_swt + (((size_t)(b * 8 + h) * 64 + g0) * 16384) + nin + t0;
    #pragma unroll
    for (int j = 0; j < 8; ++j)
        *(float2*)(gb + (size_t)j * 16384) = make_float2(w0[j], w1[j]);

    // norm partials: reduce token dim (shfl over ty within warp, smem across warps)
    float pn[8];
    #pragma unroll
    for (int j = 0; j < 8; ++j) {
        float p = w0[j] + w1[j];
        p += __shfl_xor_sync(0xffffffffu, p, 8);
        p += __shfl_xor_sync(0xffffffffu, p, 16);
        pn[j] = p;
    }
    if (lane < 8) {
        #pragma unroll
        for (int j = 0; j < 8; ++j) NP[tid >> 5][lane * 8 + j] = pn[j];
    }
    __syncthreads();
    if (tid < 64) {
        float s = 0.f;
        #pragma unroll
        for (int w = 0; w < 8; ++w) s += NP[w][tid];
        g_npart[((size_t)(b * 8 + h) * 256 + (blockIdx.x & 255)) * 64 + tid] = s;
    }
}

// ---------------- slice_token: tf32 mma GEMM over K=n ------------------------
// grid (64 bh, 16 chunks of 1024n), 256 threads; warp tile 16M x 32N.
__global__ void __launch_bounds__(256)
slicetoken_kernel()
{
    extern __shared__ float sm2[];   // 2 stages x (As 64x68 + Bs 64x68)
    const int tid  = threadIdx.x;
    const int wid  = tid >> 5;
    const int lane = tid & 31;
    const int g    = lane >> 2;
    const int t4   = lane & 3;
    const int bh   = blockIdx.x;
    const int b    = bh >> 3, h = bh & 7;
    const int n0   = blockIdx.y * 1024;

    const float* arow = g_swt + (size_t)bh * 64 * 16384;
    const float* brow = g_fxt + ((size_t)b * 512 + h * 64) * 16384;

    auto load = [&](int kt, int s) {
        float* base = sm2 + s * 8704;
        const int nn = n0 + kt * 64;
        #pragma unroll
        for (int i = 0; i < 4; ++i) {
            int f = tid + 256 * i;
            int r = f >> 4, q = f & 15;
            CP16(smem_u32(base + r * 68 + q * 4),
                 arow + (size_t)r * 16384 + nn + q * 4);
            CP16(smem_u32(base + 4352 + r * 68 + q * 4),
                 brow + (size_t)r * 16384 + nn + q * 4);
        }
    };

    float acc[4][4] = {};
    const int m0  = (wid & 3) * 16;
    const int nc0 = (wid >> 2) * 32;

    load(0, 0); CP_COMMIT();
    for (int kt = 0; kt < 16; ++kt) {
        if (kt + 1 < 16) { load(kt + 1, (kt + 1) & 1); CP_COMMIT(); CP_WAIT(1); }
        else             { CP_WAIT(0); }
        __syncthreads();
        const float* As_ = sm2 + (kt & 1) * 8704;
        const float* Bs_ = As_ + 4352;
        #pragma unroll
        for (int ks = 0; ks < 8; ++ks) {
            const int kk = ks * 8;
            unsigned af[4];
            const float* p0 = As_ + (m0 + g) * 68 + kk + t4;
            const float* p1 = p0 + 544;
            af[0] = __float_as_uint(p0[0]);
            af[1] = __float_as_uint(p1[0]);
            af[2] = __float_as_uint(p0[4]);
            af[3] = __float_as_uint(p1[4]);
            #pragma unroll
            for (int nt = 0; nt < 4; ++nt) {
                unsigned bf[2];
                const float* p = Bs_ + (nc0 + nt * 8 + g) * 68 + kk + t4;
                bf[0] = __float_as_uint(p[0]);
                bf[1] = __float_as_uint(p[4]);
                mma_tf32(acc[nt], af, bf);
            }
        }
        __syncthreads();
    }

    float* p = g_part + ((size_t)blockIdx.y * 64 + bh) * 4096;
    #pragma unroll
    for (int nt = 0; nt < 4; ++nt) {
        const int col = nc0 + nt * 8 + t4 * 2;
        *(float2*)(p + (m0 + g) * 64 + col)     = make_float2(acc[nt][0], acc[nt][1]);
        *(float2*)(p + (m0 + 8 + g) * 64 + col) = make_float2(acc[nt][2], acc[nt][3]);
    }
}

// ---------------- reduce partials --------------------------------------------
__global__ void reduce_token_kernel()
{
    int idx = blockIdx.x * 512 + threadIdx.x;
    float s = 0.f;
    #pragma unroll
    for (int ch = 0; ch < 16; ++ch) s += g_part[(size_t)ch * 262144 + idx];
    g_st[idx] = s;
    if (idx < 4096) {
        int bh = idx >> 6, gg = idx & 63;
        float ns = 0.f;
        for (int t = 0; t < 256; ++t)
            ns += g_npart[((size_t)bh * 256 + t) * 64 + gg];
        g_norm[idx] = ns;
    }
}

// ---------------- normalize + QKV --------------------------------------------
__global__ void qkv_kernel(const float* __restrict__ wq,
                           const float* __restrict__ wk,
                           const float* __restrict__ wv)
{
    __shared__ float S[64][65];
    int bh = blockIdx.x;
    int tid = threadIdx.x;
    const float* st = g_st + (size_t)bh * 4096;
    const float* nm = g_norm + bh * 64;
    for (int i = tid; i < 4096; i += 256)
        S[i >> 6][i & 63] = st[i] / (nm[i >> 6] + 1e-5f);
    __syncthreads();

    int g = tid >> 2;
    int d0 = (tid & 3) * 16;
    for (int d = d0; d < d0 + 16; ++d) {
        float q = 0.f, k = 0.f, v = 0.f;
        #pragma unroll 8
        for (int c = 0; c < 64; ++c) {
            float s = S[g][c];
            q += s * wq[d * 64 + c];
            k += s * wk[d * 64 + c];
            v += s * wv[d * 64 + c];
        }
        int o = bh * 4096 + g * 64 + d;
        g_q[o] = q; g_k[o] = k; g_v[o] = v;
    }
}

// ---------------- 64x64 attention per (b,h) ----------------------------------
__global__ void attn_kernel()
{
    __shared__ float X[64][65];
    __shared__ float Y[64][65];
    int bh = blockIdx.x;
    int tid = threadIdx.x;
    for (int i = tid; i < 4096; i += 256) {
        X[i >> 6][i & 63] = g_q[bh * 4096 + i];
        Y[i >> 6][i & 63] = g_k[bh * 4096 + i];
    }
    __syncthreads();

    int g = tid >> 2;
    int k0 = (tid & 3) * 16;
    float a[16];
    #pragma unroll
    for (int i = 0; i < 16; ++i) {
        float s = 0.f;
        for (int c = 0; c < 64; ++c) s += X[g][c] * Y[k0 + i][c];
        a[i] = s * 0.125f;
    }
    __syncthreads();
    #pragma unroll
    for (int i = 0; i < 16; ++i) X[g][k0 + i] = a[i];
    for (int i = tid; i < 4096; i += 256)
        Y[i >> 6][i & 63] = g_v[bh * 4096 + i];
    __syncthreads();

    if (tid < 64) {
        float mx = -1e30f;
        for (int k = 0; k < 64; ++k) mx = fmaxf(mx, X[tid][k]);
        float s = 0.f;
        for (int k = 0; k < 64; ++k) { float e = __expf(X[tid][k] - mx); X[tid][k] = e; s += e; }
        float inv = 1.f / s;
        for (int k = 0; k < 64; ++k) X[tid][k] *= inv;
    }
    __syncthreads();

    for (int d = k0; d < k0 + 16; ++d) {
        float o = 0.f;
        for (int k = 0; k < 64; ++k) o += X[g][k] * Y[k][d];
        g_os[bh * 4096 + g * 64 + d] = o;
    }
}

// ---------------- out_x scatter-back (reads g_swt directly) ------------------
__global__ void outx_kernel()
{
    __shared__ float SWt[64][68];
    __shared__ float OS[64][64];
    int ntile = blockIdx.x;
    int bh = blockIdx.y;
    int b = bh >> 3, h = bh & 7;
    int n0 = ntile * 64;
    int tid = threadIdx.x;

    #pragma unroll
    for (int i = 0; i < 4; ++i) {
        int f = tid + 256 * i;
        int gg = f >> 4, q = f & 15;
        float4 v = *(const float4*)(g_swt + ((size_t)bh * 64 + gg) * 16384 + n0 + q * 4);
        *(float4*)&SWt[gg][q * 4] = v;
    }
    #pragma unroll
    for (int i = 0; i < 4; ++i) {
        int f = tid + 256 * i;
        int gg = f >> 4, c4 = f & 15;
        *(float4*)&OS[gg][c4 * 4] = *(const float4*)(g_os + (size_t)bh * 4096 + gg * 64 + c4 * 4);
    }
    __syncthreads();

    int ty = tid >> 4, tx = tid & 15;
    float acc[4][4] = {};
    #pragma unroll
    for (int kk = 0; kk < 64; ++kk) {
        float4 a  = *(const float4*)&SWt[kk][ty * 4];
        float4 bv = *(const float4*)&OS[kk][tx * 4];
        acc[0][0] += a.x * bv.x; acc[0][1] += a.x * bv.y; acc[0][2] += a.x * bv.z; acc[0][3] += a.x * bv.w;
        acc[1][0] += a.y * bv.x; acc[1][1] += a.y * bv.y; acc[1][2] += a.y * bv.z; acc[1][3] += a.y * bv.w;
        acc[2][0] += a.z * bv.x; acc[2][1] += a.z * bv.y; acc[2][2] += a.z * bv.z; acc[2][3] += a.z * bv.w;
        acc[3][0] += a.w * bv.x; acc[3][1] += a.w * bv.y; acc[3][2] += a.w * bv.z; acc[3][3] += a.w * bv.w;
    }
    #pragma unroll
    for (int i = 0; i < 4; ++i) {
        int n = n0 + ty * 4 + i;
        float* o = g_ox + ((size_t)(b * N_ + n)) * 512 + h * 64 + tx * 4;
        #pragma unroll
        for (int j = 0; j < 4; ++j) o[j] = acc[i][j];
    }
}

// ---------------- final projection GEMM --------------------------------------
__global__ void final_kernel(const float* __restrict__ out_w,
                             const float* __restrict__ out_b,
                             float* __restrict__ out)
{
    __shared__ float As[32][68];
    __shared__ float Bs[32][68];
    int m0 = blockIdx.x * 64;
    int d0 = blockIdx.y * 64;
    int tid = threadIdx.x;
    int ty = tid >> 4, tx = tid & 15;
    float acc[4][4] = {};

    for (int k0 = 0; k0 < 512; k0 += 32) {
        #pragma unroll
        for (int i = 0; i < 2; ++i) {
            int f = tid + 256 * i;
            int r = f >> 3, kg = f & 7;
            float4 v = *(const float4*)(g_ox + (size_t)(m0 + r) * 512 + k0 + kg * 4);
            As[kg * 4 + 0][r] = v.x;
            As[kg * 4 + 1][r] = v.y;
            As[kg * 4 + 2][r] = v.z;
            As[kg * 4 + 3][r] = v.w;
        }
        #pragma unroll
        for (int i = 0; i < 2; ++i) {
            int f = tid + 256 * i;
            int dd = f >> 3, kg = f & 7;
            float4 v = *(const float4*)(out_w + (size_t)(d0 + dd) * 512 + k0 + kg * 4);
            Bs[kg * 4 + 0][dd] = v.x;
            Bs[kg * 4 + 1][dd] = v.y;
            Bs[kg * 4 + 2][dd] = v.z;
            Bs[kg * 4 + 3][dd] = v.w;
        }
        __syncthreads();
        #pragma unroll
        for (int kk = 0; kk < 32; ++kk) {
            float4 a  = *(const float4*)&As[kk][ty * 4];
            float4 bv = *(const float4*)&Bs[kk][tx * 4];
            acc[0][0] += a.x * bv.x; acc[0][1] += a.x * bv.y; acc[0][2] += a.x * bv.z; acc[0][3] += a.x * bv.w;
            acc[1][0] += a.y * bv.x; acc[1][1] += a.y * bv.y; acc[1][2] += a.y * bv.z; acc[1][3] += a.y * bv.w;
            acc[2][0] += a.z * bv.x; acc[2][1] += a.z * bv.y; acc[2][2] += a.z * bv.z; acc[2][3] += a.z * bv.w;
            acc[3][0] += a.w * bv.x; acc[3][1] += a.w * bv.y; acc[3][2] += a.w * bv.z; acc[3][3] += a.w * bv.w;
        }
        __syncthreads();
    }
    #pragma unroll
    for (int i = 0; i < 4; ++i) {
        int m = m0 + ty * 4 + i;
        float* o = out + (size_t)m * 128 + d0 + tx * 4;
        #pragma unroll
        for (int j = 0; j < 4; ++j)
            o[j] = acc[i][j] + out_b[d0 + tx * 4 + j];
    }
}

// ---------------- launch ------------------------------------------------------
extern "C" void kernel_launch(void* const* d_in, const int* in_sizes, int n_in,
                              void* d_out, int out_size)
{
    const float* x          = (const float*)d_in[0];
    const float* conv_fx_w  = (const float*)d_in[1];
    const float* conv_fx_b  = (const float*)d_in[2];
    const float* conv_x_w   = (const float*)d_in[3];
    const float* conv_x_b   = (const float*)d_in[4];
    const float* slice_w    = (const float*)d_in[5];
    const float* slice_b    = (const float*)d_in[6];
    const float* temperature= (const float*)d_in[7];
    const float* wq         = (const float*)d_in[8];
    const float* wk         = (const float*)d_in[9];
    const float* wv         = (const float*)d_in[10];
    const float* out_w      = (const float*)d_in[11];
    const float* out_b      = (const float*)d_in[12];
    float* out = (float*)d_out;

    cudaFuncSetAttribute(conv_mma_kernel,
                         cudaFuncAttributeMaxDynamicSharedMemorySize, 165888);
    cudaFuncSetAttribute(slicetoken_kernel,
                         cudaFuncAttributeMaxDynamicSharedMemorySize, 69632);

    wprep_kernel<<<4608, 256>>>(conv_fx_w, conv_x_w);
    wprep_x_kernel<<<16384, 256>>>(x);
    conv_mma_kernel<<<dim3(1024, 4), 256, 165888>>>(conv_fx_b, conv_x_b);
    sliceweights_kernel<<<dim3(2048, 8), 256>>>(slice_w, slice_b, temperature);
    slicetoken_kernel<<<dim3(64, 16), 256, 69632>>>();
    reduce_token_kernel<<<512, 512>>>();
    qkv_kernel<<<64, 256>>>(wq, wk, wv);
    attn_kernel<<<64, 256>>>();
    outx_kernel<<<dim3(256, 64), 256>>>();
    final_kernel<<<dim3(2048, 2), 256>>>(out_w, out_b, out);
}

// round 6
// speedup vs baseline: 6.7493x; 1.0589x over previous
#include <cuda_runtime.h>

#define B_     8
#define N_     16384
#define DIM_   128

// ---------------- scratch (device globals) ----------------------------------
__device__ float g_xr[16777216];   // tf32-rounded x (B,N,128)
__device__ float g_fx[67108864];   // conv_fx output (B,N,512)
__device__ float g_fxt[67108864];  // conv_fx TRANSPOSED (B,512co,16384n)
__device__ float g_xm[67108864];   // conv_x output (B,N,512)
__device__ float g_swt[67108864];  // slice weights TRANSPOSED (B,H,64g,16384n)
__device__ float g_ox[67108864];   // out_x (B,N,512)
__device__ float g_part[4194304];  // 16 chunks x 64 bh x 4096
__device__ float g_npart[1048576]; // 64 bh x 128 tiles x 64 g
__device__ float g_st[262144];
__device__ float g_norm[4096];
__device__ float g_q[262144];
__device__ float g_k[262144];
__device__ float g_v[262144];
__device__ float g_os[262144];
__device__ float g_wt[1179648];    // tf32 weights [1024 co][1152 k]

__device__ __forceinline__ unsigned cvt_tf32(float f) {
    unsigned u;
    asm("cvt.rna.tf32.f32 %0, %1;" : "=r"(u) : "f"(f));
    return u;
}
__device__ __forceinline__ void split_tf32(float v, unsigned& hi, unsigned& lo) {
    hi = cvt_tf32(v);
    lo = cvt_tf32(v - __uint_as_float(hi));
}
__device__ __forceinline__ unsigned smem_u32(const void* p) {
    unsigned a;
    asm("{ .reg .u64 t; cvta.to.shared.u64 t, %1; cvt.u32.u64 %0, t; }"
        : "=r"(a) : "l"(p));
    return a;
}
__device__ __forceinline__ void mma_tf32(float* c, const unsigned* a, const unsigned* b) {
    asm volatile("mma.sync.aligned.m16n8k8.row.col.f32.tf32.tf32.f32 "
                 "{%0,%1,%2,%3}, {%4,%5,%6,%7}, {%8,%9}, {%0,%1,%2,%3};"
                 : "+f"(c[0]), "+f"(c[1]), "+f"(c[2]), "+f"(c[3])
                 : "r"(a[0]), "r"(a[1]), "r"(a[2]), "r"(a[3]),
                   "r"(b[0]), "r"(b[1]));
}
#define CP16(dst, src) \
    asm volatile("cp.async.cg.shared.global [%0], [%1], 16;" :: "r"(dst), "l"(src))
#define CP16Z(dst, src, sz) \
    asm volatile("cp.async.cg.shared.global [%0], [%1], 16, %2;" :: "r"(dst), "l"(src), "r"(sz))
#define CP_COMMIT() asm volatile("cp.async.commit_group;")
#define CP_WAIT(n)  asm volatile("cp.async.wait_group %0;" :: "n"(n))

// ---------------- prep: weights + x tf32 rounding ---------------------------
__global__ void wprep_kernel(const float* __restrict__ wfx,
                             const float* __restrict__ wx)
{
    int idx = blockIdx.x * 256 + threadIdx.x;
    if (idx >= 1179648) return;
    int co = idx / 1152;
    int k  = idx - co * 1152;
    const float* w = (co < 512) ? wfx : wx;
    int c = (co < 512) ? co : co - 512;
    g_wt[idx] = __uint_as_float(cvt_tf32(w[(size_t)k * 512 + c]));
}
__global__ void wprep_x_kernel(const float* __restrict__ x)
{
    int idx = (blockIdx.x * 256 + threadIdx.x) * 4;
    float4 v = *(const float4*)(x + idx);
    uint4 u;
    u.x = cvt_tf32(v.x); u.y = cvt_tf32(v.y);
    u.z = cvt_tf32(v.z); u.w = cvt_tf32(v.w);
    *(uint4*)(g_xr + idx) = u;
}

// ---------------- conv: implicit GEMM, tf32 mma, cp.async 3-stage -----------
// grid (1024 rows, 4 ctiles of 256co), 256 threads, warp tile 64x64.
__global__ void __launch_bounds__(256)
conv_mma_kernel(const float* __restrict__ bfx, const float* __restrict__ bx)
{
    extern __shared__ float sm[];
    const int tid  = threadIdx.x;
    const int wid  = tid >> 5;
    const int lane = tid & 31;
    const int g    = lane >> 2;
    const int t4   = lane & 3;
    const int warpM = wid & 1;
    const int warpN = wid >> 1;

    const int row = blockIdx.x;
    const int b   = row >> 7;
    const int y   = row & 127;
    const int ct  = blockIdx.y;          // 0..3
    const int co0 = ct * 256;

    float acc[4][8][4] = {};

    auto load_stage = [&](int c, int s) {
        float* base = sm + s * 13824;
        const int tap = c >> 2;
        const int dy = tap / 3 - 1, dx = tap % 3 - 1;
        const int yy = y + dy;
        const bool rowok = (unsigned)yy < 128u;
        const int ci0 = (c & 3) * 32;
        const int k0w = tap * 128 + ci0;
        const float* xb = g_xr + ((size_t)(b * 128 + (rowok ? yy : 0)) * 128) * 128;
        #pragma unroll
        for (int i = 0; i < 4; ++i) {
            int f = tid + 256 * i;
            int r = f >> 3, q = f & 7;
            int xp = r + dx;
            bool ok = rowok && (unsigned)xp < 128u;
            const float* src = xb + (size_t)(ok ? xp : 0) * 128 + ci0 + q * 4;
            CP16Z(smem_u32(base + r * 36 + q * 4), src, ok ? 16 : 0);
        }
        #pragma unroll
        for (int i = 0; i < 8; ++i) {
            int f = tid + 256 * i;
            int r = f >> 3, q = f & 7;
            const float* src = g_wt + (size_t)(co0 + r) * 1152 + k0w + q * 4;
            CP16(smem_u32(base + 4608 + r * 36 + q * 4), src);
        }
    };
    auto compute = [&](int s) {
        const float* As_ = sm + s * 13824;
        const float* Bs_ = As_ + 4608;
        const int m0 = warpM * 64;
        const int n0 = warpN * 64;
        #pragma unroll
        for (int ks = 0; ks < 4; ++ks) {
            const int kk = ks * 8;
            unsigned af[4][4];
            #pragma unroll
            for (int mt = 0; mt < 4; ++mt) {
                const float* p0 = As_ + (m0 + mt * 16 + g) * 36 + kk + t4;
                const float* p1 = p0 + 288;
                af[mt][0] = __float_as_uint(p0[0]);
                af[mt][1] = __float_as_uint(p1[0]);
                af[mt][2] = __float_as_uint(p0[4]);
                af[mt][3] = __float_as_uint(p1[4]);
            }
            unsigned bf[8][2];
            #pragma unroll
            for (int nt = 0; nt < 8; ++nt) {
                const float* p = Bs_ + (n0 + nt * 8 + g) * 36 + kk + t4;
                bf[nt][0] = __float_as_uint(p[0]);
                bf[nt][1] = __float_as_uint(p[4]);
            }
            #pragma unroll
            for (int mt = 0; mt < 4; ++mt)
                #pragma unroll
                for (int nt = 0; nt < 8; ++nt)
                    mma_tf32(acc[mt][nt], af[mt], bf[nt]);
        }
    };

    load_stage(0, 0); CP_COMMIT();
    load_stage(1, 1); CP_COMMIT();

    for (int c = 0; c < 36; ++c) {
        if (c + 2 < 36) {
            load_stage(c + 2, (c + 2) % 3);
            CP_COMMIT();
            CP_WAIT(2);                  // stage c resident; c+1, c+2 in flight
        } else if (c < 35) {
            CP_WAIT(1);
        } else {
            CP_WAIT(0);
        }
        __syncthreads();
        compute(c % 3);
        __syncthreads();
    }

    // epilogue: normal layout writes, fully coalesced
    float* outp = (ct < 2) ? g_fx : g_xm;
    const int cin = (ct & 1) * 256;
    const float* biasp = ((ct < 2) ? bfx : bx) + cin;
    float* outb = outp + ((size_t)(b * N_ + y * 128)) * 512 + cin;
    #pragma unroll
    for (int mt = 0; mt < 4; ++mt) {
        const int m = warpM * 64 + mt * 16 + g;
        #pragma unroll
        for (int nt = 0; nt < 8; ++nt) {
            const int nl = warpN * 64 + nt * 8 + t4 * 2;
            float b0 = __ldg(biasp + nl), b1 = __ldg(biasp + nl + 1);
            *(float2*)(outb + (size_t)m * 512 + nl) =
                make_float2(acc[mt][nt][0] + b0, acc[mt][nt][1] + b1);
            *(float2*)(outb + (size_t)(m + 8) * 512 + nl) =
                make_float2(acc[mt][nt][2] + b0, acc[mt][nt][3] + b1);
        }
    }
}

// ---------------- transpose fx: (B,N,512) -> (B,512,N) ----------------------
__global__ void transpose_fx_kernel()
{
    __shared__ float tile[64][68];
    const int tid = threadIdx.x;
    const int n0  = blockIdx.x * 64;
    const int co0 = blockIdx.y * 64;
    const int b   = blockIdx.z;

    const float* src = g_fx + ((size_t)(b * N_ + n0)) * 512 + co0;
    #pragma unroll
    for (int i = 0; i < 4; ++i) {
        int f = tid + 256 * i;          // 1024 float4 = 64n x 16c4
        int n = f >> 4, c4 = f & 15;
        float4 v = *(const float4*)(src + (size_t)n * 512 + c4 * 4);
        tile[c4 * 4 + 0][n] = v.x;
        tile[c4 * 4 + 1][n] = v.y;
        tile[c4 * 4 + 2][n] = v.z;
        tile[c4 * 4 + 3][n] = v.w;
    }
    __syncthreads();
    float* dst = g_fxt + ((size_t)(b * 512 + co0)) * 16384 + n0;
    #pragma unroll
    for (int i = 0; i < 4; ++i) {
        int f = tid + 256 * i;          // 64co x 16n4
        int c = f >> 4, n4 = f & 15;
        float4 v = *(const float4*)&tile[c][n4 * 4];
        *(float4*)(dst + (size_t)c * 16384 + n4 * 4) = v;
    }
}

// ---------------- slice weights: GEMM + softmax, 128-token tiles ------------
// grid (1024 = b*128tiles, 8 heads), 256 threads; thread = 4 tok x 8 g.
// dyn smem: Xst[64][132] @0, Wt[64][68] @8448, NP[8][64] @12800 (floats)
__global__ void __launch_bounds__(256)
sliceweights_kernel(const float* __restrict__ slice_w,
                    const float* __restrict__ slice_b,
                    const float* __restrict__ temperature)
{
    extern __shared__ float dsm[];
    float* Xst = dsm;            // [c][t], stride 132
    float* Wt  = dsm + 8448;     // [c][g], stride 68
    float* NP  = dsm + 12800;    // [warp][g]

    const int tid  = threadIdx.x;
    const int h    = blockIdx.y;
    const int b    = blockIdx.x >> 7;
    const int tile = blockIdx.x & 127;
    const int bn0  = b * N_ + tile * 128;
    const int nin  = tile * 128;

    for (int i = tid; i < 4096; i += 256) {
        int gg = i >> 6, c = i & 63;
        Wt[c * 68 + gg] = slice_w[i];
    }
    #pragma unroll
    for (int i = 0; i < 8; ++i) {
        int f = tid + 256 * i;          // 2048 float4 = 128t x 16c4
        int t = f >> 4, c4 = f & 15;
        float4 v = *(const float4*)(g_xm + (size_t)(bn0 + t) * 512 + h * 64 + c4 * 4);
        Xst[(c4 * 4 + 0) * 132 + t] = v.x;
        Xst[(c4 * 4 + 1) * 132 + t] = v.y;
        Xst[(c4 * 4 + 2) * 132 + t] = v.z;
        Xst[(c4 * 4 + 3) * 132 + t] = v.w;
    }
    __syncthreads();

    const int tx = tid & 7;
    const int ty = tid >> 3;
    const int t0 = ty * 4;
    const int g0 = tx * 8;
    const int lane = tid & 31;
    const int warp = tid >> 5;

    float acc[4][8] = {};
    #pragma unroll 4
    for (int c = 0; c < 64; ++c) {
        float4 a  = *(const float4*)&Xst[c * 132 + t0];
        float4 b0 = *(const float4*)&Wt[c * 68 + g0];
        float4 b1 = *(const float4*)&Wt[c * 68 + g0 + 4];
        #pragma unroll
        for (int i = 0; i < 4; ++i) {
            float ai = (i == 0) ? a.x : (i == 1) ? a.y : (i == 2) ? a.z : a.w;
            acc[i][0] += ai * b0.x; acc[i][1] += ai * b0.y;
            acc[i][2] += ai * b0.z; acc[i][3] += ai * b0.w;
            acc[i][4] += ai * b1.x; acc[i][5] += ai * b1.y;
            acc[i][6] += ai * b1.z; acc[i][7] += ai * b1.w;
        }
    }

    float tv = temperature[h];
    tv = fminf(fmaxf(tv, 0.1f), 5.0f);
    float invt = 1.f / tv;
    float bias[8];
    #pragma unroll
    for (int j = 0; j < 8; ++j) bias[j] = __ldg(slice_b + g0 + j);

    float w[4][8];
    #pragma unroll
    for (int i = 0; i < 4; ++i) {
        float l[8];
        #pragma unroll
        for (int j = 0; j < 8; ++j) l[j] = (acc[i][j] + bias[j]) * invt;
        float mx = l[0];
        #pragma unroll
        for (int j = 1; j < 8; ++j) mx = fmaxf(mx, l[j]);
        #pragma unroll
        for (int o = 1; o < 8; o <<= 1)
            mx = fmaxf(mx, __shfl_xor_sync(0xffffffffu, mx, o));
        float s = 0.f;
        #pragma unroll
        for (int j = 0; j < 8; ++j) { l[j] = __expf(l[j] - mx); s += l[j]; }
        #pragma unroll
        for (int o = 1; o < 8; o <<= 1)
            s += __shfl_xor_sync(0xffffffffu, s, o);
        float inv = 1.f / s;
        #pragma unroll
        for (int j = 0; j < 8; ++j) w[i][j] = l[j] * inv;
    }

    // transposed write: g_swt[(b*8+h)*64+g][n], float4 along n
    const int bh = b * 8 + h;
    float* gb = g_swt + (((size_t)bh * 64 + g0) * 16384) + nin + t0;
    #pragma unroll
    for (int j = 0; j < 8; ++j)
        *(float4*)(gb + (size_t)j * 16384) =
            make_float4(w[0][j], w[1][j], w[2][j], w[3][j]);

    // norm partials (sum over tokens)
    float pn[8];
    #pragma unroll
    for (int j = 0; j < 8; ++j) {
        float p = w[0][j] + w[1][j] + w[2][j] + w[3][j];
        p += __shfl_xor_sync(0xffffffffu, p, 8);
        p += __shfl_xor_sync(0xffffffffu, p, 16);
        pn[j] = p;
    }
    if (lane < 8) {
        #pragma unroll
        for (int j = 0; j < 8; ++j) NP[warp * 64 + lane * 8 + j] = pn[j];
    }
    __syncthreads();
    if (tid < 64) {
        float s = 0.f;
        #pragma unroll
        for (int wv = 0; wv < 8; ++wv) s += NP[wv * 64 + tid];
        g_npart[((size_t)bh * 128 + tile) * 64 + tid] = s;
    }
}

// ---------------- slice_token: tf32 hi/lo mma GEMM over K=n ------------------
__global__ void __launch_bounds__(256)
slicetoken_kernel()
{
    extern __shared__ float sm2[];   // 2 stages x (As 64x68 + Bs 64x68)
    const int tid  = threadIdx.x;
    const int wid  = tid >> 5;
    const int lane = tid & 31;
    const int g    = lane >> 2;
    const int t4   = lane & 3;
    const int bh   = blockIdx.x;
    const int b    = bh >> 3, h = bh & 7;
    const int n0   = blockIdx.y * 1024;

    const float* arow = g_swt + (size_t)bh * 64 * 16384;
    const float* brow = g_fxt + ((size_t)b * 512 + h * 64) * 16384;

    auto load = [&](int kt, int s) {
        float* base = sm2 + s * 8704;
        const int nn = n0 + kt * 64;
        #pragma unroll
        for (int i = 0; i < 4; ++i) {
            int f = tid + 256 * i;
            int r = f >> 4, q = f & 15;
            CP16(smem_u32(base + r * 68 + q * 4),
                 arow + (size_t)r * 16384 + nn + q * 4);
            CP16(smem_u32(base + 4352 + r * 68 + q * 4),
                 brow + (size_t)r * 16384 + nn + q * 4);
        }
    };

    float acc[4][4] = {};
    const int m0  = (wid & 3) * 16;
    const int nc0 = (wid >> 2) * 32;

    load(0, 0); CP_COMMIT();
    for (int kt = 0; kt < 16; ++kt) {
        if (kt + 1 < 16) { load(kt + 1, (kt + 1) & 1); CP_COMMIT(); CP_WAIT(1); }
        else             { CP_WAIT(0); }
        __syncthreads();
        const float* As_ = sm2 + (kt & 1) * 8704;
        const float* Bs_ = As_ + 4352;
        #pragma unroll
        for (int ks = 0; ks < 8; ++ks) {
            const int kk = ks * 8;
            unsigned afh[4], afl[4];
            const float* p0 = As_ + (m0 + g) * 68 + kk + t4;
            const float* p1 = p0 + 544;
            split_tf32(p0[0], afh[0], afl[0]);
            split_tf32(p1[0], afh[1], afl[1]);
            split_tf32(p0[4], afh[2], afl[2]);
            split_tf32(p1[4], afh[3], afl[3]);
            #pragma unroll
            for (int nt = 0; nt < 4; ++nt) {
                unsigned bfh[2], bfl[2];
                const float* p = Bs_ + (nc0 + nt * 8 + g) * 68 + kk + t4;
                split_tf32(p[0], bfh[0], bfl[0]);
                split_tf32(p[4], bfh[1], bfl[1]);
                mma_tf32(acc[nt], afh, bfh);
                mma_tf32(acc[nt], afl, bfh);
                mma_tf32(acc[nt], afh, bfl);
            }
        }
        __syncthreads();
    }

    float* p = g_part + ((size_t)blockIdx.y * 64 + bh) * 4096;
    #pragma unroll
    for (int nt = 0; nt < 4; ++nt) {
        const int col = nc0 + nt * 8 + t4 * 2;
        *(float2*)(p + (m0 + g) * 64 + col)     = make_float2(acc[nt][0], acc[nt][1]);
        *(float2*)(p + (m0 + 8 + g) * 64 + col) = make_float2(acc[nt][2], acc[nt][3]);
    }
}

// ---------------- reduce partials --------------------------------------------
__global__ void reduce_token_kernel()
{
    int idx = blockIdx.x * 512 + threadIdx.x;
    float s = 0.f;
    #pragma unroll
    for (int ch = 0; ch < 16; ++ch) s += g_part[(size_t)ch * 262144 + idx];
    g_st[idx] = s;
    if (idx < 4096) {
        int bh = idx >> 6, gg = idx & 63;
        float ns = 0.f;
        for (int t = 0; t < 128; ++t)
            ns += g_npart[((size_t)bh * 128 + t) * 64 + gg];
        g_norm[idx] = ns;
    }
}

// ---------------- normalize + QKV --------------------------------------------
__global__ void qkv_kernel(const float* __restrict__ wq,
                           const float* __restrict__ wk,
                           const float* __restrict__ wv)
{
    __shared__ float S[64][65];
    int bh = blockIdx.x;
    int tid = threadIdx.x;
    const float* st = g_st + (size_t)bh * 4096;
    const float* nm = g_norm + bh * 64;
    for (int i = tid; i < 4096; i += 256)
        S[i >> 6][i & 63] = st[i] / (nm[i >> 6] + 1e-5f);
    __syncthreads();

    int g = tid >> 2;
    int d0 = (tid & 3) * 16;
    for (int d = d0; d < d0 + 16; ++d) {
        float q = 0.f, k = 0.f, v = 0.f;
        #pragma unroll 8
        for (int c = 0; c < 64; ++c) {
            float s = S[g][c];
            q += s * wq[d * 64 + c];
            k += s * wk[d * 64 + c];
            v += s * wv[d * 64 + c];
        }
        int o = bh * 4096 + g * 64 + d;
        g_q[o] = q; g_k[o] = k; g_v[o] = v;
    }
}

// ---------------- 64x64 attention per (b,h) ----------------------------------
__global__ void attn_kernel()
{
    __shared__ float X[64][65];
    __shared__ float Y[64][65];
    int bh = blockIdx.x;
    int tid = threadIdx.x;
    for (int i = tid; i < 4096; i += 256) {
        X[i >> 6][i & 63] = g_q[bh * 4096 + i];
        Y[i >> 6][i & 63] = g_k[bh * 4096 + i];
    }
    __syncthreads();

    int g = tid >> 2;
    int k0 = (tid & 3) * 16;
    float a[16];
    #pragma unroll
    for (int i = 0; i < 16; ++i) {
        float s = 0.f;
        for (int c = 0; c < 64; ++c) s += X[g][c] * Y[k0 + i][c];
        a[i] = s * 0.125f;
    }
    __syncthreads();
    #pragma unroll
    for (int i = 0; i < 16; ++i) X[g][k0 + i] = a[i];
    for (int i = tid; i < 4096; i += 256)
        Y[i >> 6][i & 63] = g_v[bh * 4096 + i];
    __syncthreads();

    if (tid < 64) {
        float mx = -1e30f;
        for (int k = 0; k < 64; ++k) mx = fmaxf(mx, X[tid][k]);
        float s = 0.f;
        for (int k = 0; k < 64; ++k) { float e = __expf(X[tid][k] - mx); X[tid][k] = e; s += e; }
        float inv = 1.f / s;
        for (int k = 0; k < 64; ++k) X[tid][k] *= inv;
    }
    __syncthreads();

    for (int d = k0; d < k0 + 16; ++d) {
        float o = 0.f;
        for (int k = 0; k < 64; ++k) o += X[g][k] * Y[k][d];
        g_os[bh * 4096 + g * 64 + d] = o;
    }
}

// ---------------- out_x scatter-back (reads g_swt directly) ------------------
__global__ void outx_kernel()
{
    __shared__ float SWt[64][68];
    __shared__ float OS[64][64];
    int ntile = blockIdx.x;
    int bh = blockIdx.y;
    int b = bh >> 3, h = bh & 7;
    int n0 = ntile * 64;
    int tid = threadIdx.x;

    #pragma unroll
    for (int i = 0; i < 4; ++i) {
        int f = tid + 256 * i;
        int gg = f >> 4, q = f & 15;
        float4 v = *(const float4*)(g_swt + ((size_t)bh * 64 + gg) * 16384 + n0 + q * 4);
        *(float4*)&SWt[gg][q * 4] = v;
    }
    #pragma unroll
    for (int i = 0; i < 4; ++i) {
        int f = tid + 256 * i;
        int gg = f >> 4, c4 = f & 15;
        *(float4*)&OS[gg][c4 * 4] = *(const float4*)(g_os + (size_t)bh * 4096 + gg * 64 + c4 * 4);
    }
    __syncthreads();

    int ty = tid >> 4, tx = tid & 15;
    float acc[4][4] = {};
    #pragma unroll
    for (int kk = 0; kk < 64; ++kk) {
        float4 a;
        a.x = SWt[kk][ty * 4 + 0];
        a.y = SWt[kk][ty * 4 + 1];
        a.z = SWt[kk][ty * 4 + 2];
        a.w = SWt[kk][ty * 4 + 3];
        float4 bv = *(const float4*)&OS[kk][tx * 4];
        acc[0][0] += a.x * bv.x; acc[0][1] += a.x * bv.y; acc[0][2] += a.x * bv.z; acc[0][3] += a.x * bv.w;
        acc[1][0] += a.y * bv.x; acc[1][1] += a.y * bv.y; acc[1][2] += a.y * bv.z; acc[1][3] += a.y * bv.w;
        acc[2][0] += a.z * bv.x; acc[2][1] += a.z * bv.y; acc[2][2] += a.z * bv.z; acc[2][3] += a.z * bv.w;
        acc[3][0] += a.w * bv.x; acc[3][1] += a.w * bv.y; acc[3][2] += a.w * bv.z; acc[3][3] += a.w * bv.w;
    }
    #pragma unroll
    for (int i = 0; i < 4; ++i) {
        int n = n0 + ty * 4 + i;
        float* o = g_ox + ((size_t)(b * N_ + n)) * 512 + h * 64 + tx * 4;
        #pragma unroll
        for (int j = 0; j < 4; ++j) o[j] = acc[i][j];
    }
}

// ---------------- final projection GEMM --------------------------------------
__global__ void final_kernel(const float* __restrict__ out_w,
                             const float* __restrict__ out_b,
                             float* __restrict__ out)
{
    __shared__ float As[32][68];
    __shared__ float Bs[32][68];
    int m0 = blockIdx.x * 64;
    int d0 = blockIdx.y * 64;
    int tid = threadIdx.x;
    int ty = tid >> 4, tx = tid & 15;
    float acc[4][4] = {};

    for (int k0 = 0; k0 < 512; k0 += 32) {
        #pragma unroll
        for (int i = 0; i < 2; ++i) {
            int f = tid + 256 * i;
            int r = f >> 3, kg = f & 7;
            float4 v = *(const float4*)(g_ox + (size_t)(m0 + r) * 512 + k0 + kg * 4);
            As[kg * 4 + 0][r] = v.x;
            As[kg * 4 + 1][r] = v.y;
            As[kg * 4 + 2][r] = v.z;
            As[kg * 4 + 3][r] = v.w;
        }
        #pragma unroll
        for (int i = 0; i < 2; ++i) {
            int f = tid + 256 * i;
            int dd = f >> 3, kg = f & 7;
            float4 v = *(const float4*)(out_w + (size_t)(d0 + dd) * 512 + k0 + kg * 4);
            Bs[kg * 4 + 0][dd] = v.x;
            Bs[kg * 4 + 1][dd] = v.y;
            Bs[kg * 4 + 2][dd] = v.z;
            Bs[kg * 4 + 3][dd] = v.w;
        }
        __syncthreads();
        #pragma unroll
        for (int kk = 0; kk < 32; ++kk) {
            float4 a  = *(const float4*)&As[kk][ty * 4];
            float4 bv = *(const float4*)&Bs[kk][tx * 4];
            acc[0][0] += a.x * bv.x; acc[0][1] += a.x * bv.y; acc[0][2] += a.x * bv.z; acc[0][3] += a.x * bv.w;
            acc[1][0] += a.y * bv.x; acc[1][1] += a.y * bv.y; acc[1][2] += a.y * bv.z; acc[1][3] += a.y * bv.w;
            acc[2][0] += a.z * bv.x; acc[2][1] += a.z * bv.y; acc[2][2] += a.z * bv.z; acc[2][3] += a.z * bv.w;
            acc[3][0] += a.w * bv.x; acc[3][1] += a.w * bv.y; acc[3][2] += a.w * bv.z; acc[3][3] += a.w * bv.w;
        }
        __syncthreads();
    }
    #pragma unroll
    for (int i = 0; i < 4; ++i) {
        int m = m0 + ty * 4 + i;
        float* o = out + (size_t)m * 128 + d0 + tx * 4;
        #pragma unroll
        for (int j = 0; j < 4; ++j)
            o[j] = acc[i][j] + out_b[d0 + tx * 4 + j];
    }
}

// ---------------- launch ------------------------------------------------------
extern "C" void kernel_launch(void* const* d_in, const int* in_sizes, int n_in,
                              void* d_out, int out_size)
{
    const float* x          = (const float*)d_in[0];
    const float* conv_fx_w  = (const float*)d_in[1];
    const float* conv_fx_b  = (const float*)d_in[2];
    const float* conv_x_w   = (const float*)d_in[3];
    const float* conv_x_b   = (const float*)d_in[4];
    const float* slice_w    = (const float*)d_in[5];
    const float* slice_b    = (const float*)d_in[6];
    const float* temperature= (const float*)d_in[7];
    const float* wq         = (const float*)d_in[8];
    const float* wk         = (const float*)d_in[9];
    const float* wv         = (const float*)d_in[10];
    const float* out_w      = (const float*)d_in[11];
    const float* out_b      = (const float*)d_in[12];
    float* out = (float*)d_out;

    cudaFuncSetAttribute(conv_mma_kernel,
                         cudaFuncAttributeMaxDynamicSharedMemorySize, 165888);
    cudaFuncSetAttribute(sliceweights_kernel,
                         cudaFuncAttributeMaxDynamicSharedMemorySize, 53248);
    cudaFuncSetAttribute(slicetoken_kernel,
                         cudaFuncAttributeMaxDynamicSharedMemorySize, 69632);

    wprep_kernel<<<4608, 256>>>(conv_fx_w, conv_x_w);
    wprep_x_kernel<<<16384, 256>>>(x);
    conv_mma_kernel<<<dim3(1024, 4), 256, 165888>>>(conv_fx_b, conv_x_b);
    transpose_fx_kernel<<<dim3(256, 8, 8), 256>>>();
    sliceweights_kernel<<<dim3(1024, 8), 256, 53248>>>(slice_w, slice_b, temperature);
    slicetoken_kernel<<<dim3(64, 16), 256, 69632>>>();
    reduce_token_kernel<<<512, 512>>>();
    qkv_kernel<<<64, 256>>>(wq, wk, wv);
    attn_kernel<<<64, 256>>>();
    outx_kernel<<<dim3(256, 64), 256>>>();
    final_kernel<<<dim3(2048, 2), 256>>>(out_w, out_b, out);
}

// round 7
// speedup vs baseline: 7.6374x; 1.1316x over previous
#include <cuda_runtime.h>

#define B_     8
#define N_     16384
#define DIM_   128

// ---------------- scratch (device globals) ----------------------------------
__device__ float g_xr[16777216];   // tf32-rounded x (B,N,128)
__device__ float g_fxt[67108864];  // conv_fx TRANSPOSED (B,512co,16384n)
__device__ float g_xm[67108864];   // conv_x output (B,N,512)
__device__ float g_swt[67108864];  // slice weights TRANSPOSED (B,H,64g,16384n)
__device__ float g_part[4194304];  // 16 chunks x 64 bh x 4096
__device__ float g_npart[1048576]; // 64 bh x 128 tiles x 64 g
__device__ float g_st[262144];
__device__ float g_norm[4096];
__device__ float g_q[262144];
__device__ float g_k[262144];
__device__ float g_v[262144];
__device__ float g_os[262144];
__device__ float g_ow[524288];     // OW (B, 512k, 128d)
__device__ float g_wt[1179648];    // tf32 weights [1024 co][1152 k]

__device__ __forceinline__ unsigned cvt_tf32(float f) {
    unsigned u;
    asm("cvt.rna.tf32.f32 %0, %1;" : "=r"(u) : "f"(f));
    return u;
}
__device__ __forceinline__ void split_tf32(float v, unsigned& hi, unsigned& lo) {
    hi = cvt_tf32(v);
    lo = cvt_tf32(v - __uint_as_float(hi));
}
__device__ __forceinline__ unsigned smem_u32(const void* p) {
    unsigned a;
    asm("{ .reg .u64 t; cvta.to.shared.u64 t, %1; cvt.u32.u64 %0, t; }"
        : "=r"(a) : "l"(p));
    return a;
}
__device__ __forceinline__ void mma_tf32(float* c, const unsigned* a, const unsigned* b) {
    asm volatile("mma.sync.aligned.m16n8k8.row.col.f32.tf32.tf32.f32 "
                 "{%0,%1,%2,%3}, {%4,%5,%6,%7}, {%8,%9}, {%0,%1,%2,%3};"
                 : "+f"(c[0]), "+f"(c[1]), "+f"(c[2]), "+f"(c[3])
                 : "r"(a[0]), "r"(a[1]), "r"(a[2]), "r"(a[3]),
                   "r"(b[0]), "r"(b[1]));
}
#define CP16(dst, src) \
    asm volatile("cp.async.cg.shared.global [%0], [%1], 16;" :: "r"(dst), "l"(src))
#define CP16Z(dst, src, sz) \
    asm volatile("cp.async.cg.shared.global [%0], [%1], 16, %2;" :: "r"(dst), "l"(src), "r"(sz))
#define CP_COMMIT() asm volatile("cp.async.commit_group;")
#define CP_WAIT(n)  asm volatile("cp.async.wait_group %0;" :: "n"(n))

// ---------------- prep: weights + x tf32 rounding ---------------------------
__global__ void wprep_kernel(const float* __restrict__ wfx,
                             const float* __restrict__ wx)
{
    int idx = blockIdx.x * 256 + threadIdx.x;
    if (idx >= 1179648) return;
    int co = idx / 1152;
    int k  = idx - co * 1152;
    const float* w = (co < 512) ? wfx : wx;
    int c = (co < 512) ? co : co - 512;
    g_wt[idx] = __uint_as_float(cvt_tf32(w[(size_t)k * 512 + c]));
}
__global__ void wprep_x_kernel(const float* __restrict__ x)
{
    int idx = (blockIdx.x * 256 + threadIdx.x) * 4;
    float4 v = *(const float4*)(x + idx);
    uint4 u;
    u.x = cvt_tf32(v.x); u.y = cvt_tf32(v.y);
    u.z = cvt_tf32(v.z); u.w = cvt_tf32(v.w);
    *(uint4*)(g_xr + idx) = u;
}

// ---------------- conv: implicit GEMM, tf32 mma, cp.async 3-stage -----------
// grid (1024 rows, 4 ctiles of 256co), 256 threads, warp tile 64x64.
// ctiles 0,1 -> fx written TRANSPOSED via smem; ctiles 2,3 -> xm normal.
__global__ void __launch_bounds__(256)
conv_mma_kernel(const float* __restrict__ bfx, const float* __restrict__ bx)
{
    extern __shared__ float sm[];
    const int tid  = threadIdx.x;
    const int wid  = tid >> 5;
    const int lane = tid & 31;
    const int g    = lane >> 2;
    const int t4   = lane & 3;
    const int warpM = wid & 1;
    const int warpN = wid >> 1;

    const int row = blockIdx.x;
    const int b   = row >> 7;
    const int y   = row & 127;
    const int ct  = blockIdx.y;          // 0..3
    const int co0 = ct * 256;

    float acc[4][8][4] = {};

    auto load_stage = [&](int c, int s) {
        float* base = sm + s * 13824;
        const int tap = c >> 2;
        const int dy = tap / 3 - 1, dx = tap % 3 - 1;
        const int yy = y + dy;
        const bool rowok = (unsigned)yy < 128u;
        const int ci0 = (c & 3) * 32;
        const int k0w = tap * 128 + ci0;
        const float* xb = g_xr + ((size_t)(b * 128 + (rowok ? yy : 0)) * 128) * 128;
        #pragma unroll
        for (int i = 0; i < 4; ++i) {
            int f = tid + 256 * i;
            int r = f >> 3, q = f & 7;
            int xp = r + dx;
            bool ok = rowok && (unsigned)xp < 128u;
            const float* src = xb + (size_t)(ok ? xp : 0) * 128 + ci0 + q * 4;
            CP16Z(smem_u32(base + r * 36 + q * 4), src, ok ? 16 : 0);
        }
        #pragma unroll
        for (int i = 0; i < 8; ++i) {
            int f = tid + 256 * i;
            int r = f >> 3, q = f & 7;
            const float* src = g_wt + (size_t)(co0 + r) * 1152 + k0w + q * 4;
            CP16(smem_u32(base + 4608 + r * 36 + q * 4), src);
        }
    };
    auto compute = [&](int s) {
        const float* As_ = sm + s * 13824;
        const float* Bs_ = As_ + 4608;
        const int m0 = warpM * 64;
        const int n0 = warpN * 64;
        #pragma unroll
        for (int ks = 0; ks < 4; ++ks) {
            const int kk = ks * 8;
            unsigned af[4][4];
            #pragma unroll
            for (int mt = 0; mt < 4; ++mt) {
                const float* p0 = As_ + (m0 + mt * 16 + g) * 36 + kk + t4;
                const float* p1 = p0 + 288;
                af[mt][0] = __float_as_uint(p0[0]);
                af[mt][1] = __float_as_uint(p1[0]);
                af[mt][2] = __float_as_uint(p0[4]);
                af[mt][3] = __float_as_uint(p1[4]);
            }
            unsigned bf[8][2];
            #pragma unroll
            for (int nt = 0; nt < 8; ++nt) {
                const float* p = Bs_ + (n0 + nt * 8 + g) * 36 + kk + t4;
                bf[nt][0] = __float_as_uint(p[0]);
                bf[nt][1] = __float_as_uint(p[4]);
            }
            #pragma unroll
            for (int mt = 0; mt < 4; ++mt)
                #pragma unroll
                for (int nt = 0; nt < 8; ++nt)
                    mma_tf32(acc[mt][nt], af[mt], bf[nt]);
        }
    };

    load_stage(0, 0); CP_COMMIT();
    load_stage(1, 1); CP_COMMIT();

    for (int c = 0; c < 36; ++c) {
        if (c + 2 < 36) {
            load_stage(c + 2, (c + 2) % 3);
            CP_COMMIT();
            CP_WAIT(2);
        } else if (c < 35) {
            CP_WAIT(1);
        } else {
            CP_WAIT(0);
        }
        __syncthreads();
        compute(c % 3);
        __syncthreads();
    }

    if (ct < 2) {
        // fx: transpose in smem, write (B,512co,16384n) coalesced
        __syncthreads();
        float* T = sm;                  // [256 co][132]
        #pragma unroll
        for (int mt = 0; mt < 4; ++mt) {
            const int m = warpM * 64 + mt * 16 + g;
            #pragma unroll
            for (int nt = 0; nt < 8; ++nt) {
                const int nl = warpN * 64 + nt * 8 + t4 * 2;
                T[(size_t)nl * 132 + m]           = acc[mt][nt][0];
                T[(size_t)(nl + 1) * 132 + m]     = acc[mt][nt][1];
                T[(size_t)nl * 132 + m + 8]       = acc[mt][nt][2];
                T[(size_t)(nl + 1) * 132 + m + 8] = acc[mt][nt][3];
            }
        }
        __syncthreads();
        const float* biasp = bfx + ct * 256;
        float* dst = g_fxt + ((size_t)b * 512 + ct * 256) * 16384 + y * 128;
        #pragma unroll 4
        for (int r = 0; r < 32; ++r) {
            int co = wid * 32 + r;
            float bb = __ldg(biasp + co);
            float4 v = *(const float4*)&T[(size_t)co * 132 + lane * 4];
            v.x += bb; v.y += bb; v.z += bb; v.w += bb;
            *(float4*)(dst + (size_t)co * 16384 + lane * 4) = v;
        }
    } else {
        // xm: normal layout (B,N,512)
        const int cin = (ct - 2) * 256;
        const float* biasp = bx + cin;
        float* outb = g_xm + ((size_t)(b * N_ + y * 128)) * 512 + cin;
        #pragma unroll
        for (int mt = 0; mt < 4; ++mt) {
            const int m = warpM * 64 + mt * 16 + g;
            #pragma unroll
            for (int nt = 0; nt < 8; ++nt) {
                const int nl = warpN * 64 + nt * 8 + t4 * 2;
                float b0 = __ldg(biasp + nl), b1 = __ldg(biasp + nl + 1);
                *(float2*)(outb + (size_t)m * 512 + nl) =
                    make_float2(acc[mt][nt][0] + b0, acc[mt][nt][1] + b1);
                *(float2*)(outb + (size_t)(m + 8) * 512 + nl) =
                    make_float2(acc[mt][nt][2] + b0, acc[mt][nt][3] + b1);
            }
        }
    }
}

// ---------------- slice weights: GEMM + softmax, 128-token tiles ------------
__global__ void __launch_bounds__(256)
sliceweights_kernel(const float* __restrict__ slice_w,
                    const float* __restrict__ slice_b,
                    const float* __restrict__ temperature)
{
    extern __shared__ float dsm[];
    float* Xst = dsm;            // [c][t], stride 132
    float* Wt  = dsm + 8448;     // [c][g], stride 68
    float* NP  = dsm + 12800;    // [warp][g]

    const int tid  = threadIdx.x;
    const int h    = blockIdx.y;
    const int b    = blockIdx.x >> 7;
    const int tile = blockIdx.x & 127;
    const int bn0  = b * N_ + tile * 128;
    const int nin  = tile * 128;

    for (int i = tid; i < 4096; i += 256) {
        int gg = i >> 6, c = i & 63;
        Wt[c * 68 + gg] = slice_w[i];
    }
    #pragma unroll
    for (int i = 0; i < 8; ++i) {
        int f = tid + 256 * i;
        int t = f >> 4, c4 = f & 15;
        float4 v = *(const float4*)(g_xm + (size_t)(bn0 + t) * 512 + h * 64 + c4 * 4);
        Xst[(c4 * 4 + 0) * 132 + t] = v.x;
        Xst[(c4 * 4 + 1) * 132 + t] = v.y;
        Xst[(c4 * 4 + 2) * 132 + t] = v.z;
        Xst[(c4 * 4 + 3) * 132 + t] = v.w;
    }
    __syncthreads();

    const int tx = tid & 7;
    const int ty = tid >> 3;
    const int t0 = ty * 4;
    const int g0 = tx * 8;
    const int lane = tid & 31;
    const int warp = tid >> 5;

    float acc[4][8] = {};
    #pragma unroll 4
    for (int c = 0; c < 64; ++c) {
        float4 a  = *(const float4*)&Xst[c * 132 + t0];
        float4 b0 = *(const float4*)&Wt[c * 68 + g0];
        float4 b1 = *(const float4*)&Wt[c * 68 + g0 + 4];
        #pragma unroll
        for (int i = 0; i < 4; ++i) {
            float ai = (i == 0) ? a.x : (i == 1) ? a.y : (i == 2) ? a.z : a.w;
            acc[i][0] += ai * b0.x; acc[i][1] += ai * b0.y;
            acc[i][2] += ai * b0.z; acc[i][3] += ai * b0.w;
            acc[i][4] += ai * b1.x; acc[i][5] += ai * b1.y;
            acc[i][6] += ai * b1.z; acc[i][7] += ai * b1.w;
        }
    }

    float tv = temperature[h];
    tv = fminf(fmaxf(tv, 0.1f), 5.0f);
    float invt = 1.f / tv;
    float bias[8];
    #pragma unroll
    for (int j = 0; j < 8; ++j) bias[j] = __ldg(slice_b + g0 + j);

    float w[4][8];
    #pragma unroll
    for (int i = 0; i < 4; ++i) {
        float l[8];
        #pragma unroll
        for (int j = 0; j < 8; ++j) l[j] = (acc[i][j] + bias[j]) * invt;
        float mx = l[0];
        #pragma unroll
        for (int j = 1; j < 8; ++j) mx = fmaxf(mx, l[j]);
        #pragma unroll
        for (int o = 1; o < 8; o <<= 1)
            mx = fmaxf(mx, __shfl_xor_sync(0xffffffffu, mx, o));
        float s = 0.f;
        #pragma unroll
        for (int j = 0; j < 8; ++j) { l[j] = __expf(l[j] - mx); s += l[j]; }
        #pragma unroll
        for (int o = 1; o < 8; o <<= 1)
            s += __shfl_xor_sync(0xffffffffu, s, o);
        float inv = 1.f / s;
        #pragma unroll
        for (int j = 0; j < 8; ++j) w[i][j] = l[j] * inv;
    }

    const int bh = b * 8 + h;
    float* gb = g_swt + (((size_t)bh * 64 + g0) * 16384) + nin + t0;
    #pragma unroll
    for (int j = 0; j < 8; ++j)
        *(float4*)(gb + (size_t)j * 16384) =
            make_float4(w[0][j], w[1][j], w[2][j], w[3][j]);

    float pn[8];
    #pragma unroll
    for (int j = 0; j < 8; ++j) {
        float p = w[0][j] + w[1][j] + w[2][j] + w[3][j];
        p += __shfl_xor_sync(0xffffffffu, p, 8);
        p += __shfl_xor_sync(0xffffffffu, p, 16);
        pn[j] = p;
    }
    if (lane < 8) {
        #pragma unroll
        for (int j = 0; j < 8; ++j) NP[warp * 64 + lane * 8 + j] = pn[j];
    }
    __syncthreads();
    if (tid < 64) {
        float s = 0.f;
        #pragma unroll
        for (int wv = 0; wv < 8; ++wv) s += NP[wv * 64 + tid];
        g_npart[((size_t)bh * 128 + tile) * 64 + tid] = s;
    }
}

// ---------------- slice_token: tf32 hi/lo mma GEMM over K=n ------------------
__global__ void __launch_bounds__(256)
slicetoken_kernel()
{
    extern __shared__ float sm2[];
    const int tid  = threadIdx.x;
    const int wid  = tid >> 5;
    const int lane = tid & 31;
    const int g    = lane >> 2;
    const int t4   = lane & 3;
    const int bh   = blockIdx.x;
    const int b    = bh >> 3, h = bh & 7;
    const int n0   = blockIdx.y * 1024;

    const float* arow = g_swt + (size_t)bh * 64 * 16384;
    const float* brow = g_fxt + ((size_t)b * 512 + h * 64) * 16384;

    auto load = [&](int kt, int s) {
        float* base = sm2 + s * 8704;
        const int nn = n0 + kt * 64;
        #pragma unroll
        for (int i = 0; i < 4; ++i) {
            int f = tid + 256 * i;
            int r = f >> 4, q = f & 15;
            CP16(smem_u32(base + r * 68 + q * 4),
                 arow + (size_t)r * 16384 + nn + q * 4);
            CP16(smem_u32(base + 4352 + r * 68 + q * 4),
                 brow + (size_t)r * 16384 + nn + q * 4);
        }
    };

    float acc[4][4] = {};
    const int m0  = (wid & 3) * 16;
    const int nc0 = (wid >> 2) * 32;

    load(0, 0); CP_COMMIT();
    for (int kt = 0; kt < 16; ++kt) {
        if (kt + 1 < 16) { load(kt + 1, (kt + 1) & 1); CP_COMMIT(); CP_WAIT(1); }
        else             { CP_WAIT(0); }
        __syncthreads();
        const float* As_ = sm2 + (kt & 1) * 8704;
        const float* Bs_ = As_ + 4352;
        #pragma unroll
        for (int ks = 0; ks < 8; ++ks) {
            const int kk = ks * 8;
            unsigned afh[4], afl[4];
            const float* p0 = As_ + (m0 + g) * 68 + kk + t4;
            const float* p1 = p0 + 544;
            split_tf32(p0[0], afh[0], afl[0]);
            split_tf32(p1[0], afh[1], afl[1]);
            split_tf32(p0[4], afh[2], afl[2]);
            split_tf32(p1[4], afh[3], afl[3]);
            #pragma unroll
            for (int nt = 0; nt < 4; ++nt) {
                unsigned bfh[2], bfl[2];
                const float* p = Bs_ + (nc0 + nt * 8 + g) * 68 + kk + t4;
                split_tf32(p[0], bfh[0], bfl[0]);
                split_tf32(p[4], bfh[1], bfl[1]);
                mma_tf32(acc[nt], afh, bfh);
                mma_tf32(acc[nt], afl, bfh);
                mma_tf32(acc[nt], afh, bfl);
            }
        }
        __syncthreads();
    }

    float* p = g_part + ((size_t)blockIdx.y * 64 + bh) * 4096;
    #pragma unroll
    for (int nt = 0; nt < 4; ++nt) {
        const int col = nc0 + nt * 8 + t4 * 2;
        *(float2*)(p + (m0 + g) * 64 + col)     = make_float2(acc[nt][0], acc[nt][1]);
        *(float2*)(p + (m0 + 8 + g) * 64 + col) = make_float2(acc[nt][2], acc[nt][3]);
    }
}

// ---------------- reduce partials --------------------------------------------
__global__ void reduce_token_kernel()
{
    int idx = blockIdx.x * 512 + threadIdx.x;
    float s = 0.f;
    #pragma unroll
    for (int ch = 0; ch < 16; ++ch) s += g_part[(size_t)ch * 262144 + idx];
    g_st[idx] = s;
    if (idx < 4096) {
        int bh = idx >> 6, gg = idx & 63;
        float ns = 0.f;
        for (int t = 0; t < 128; ++t)
            ns += g_npart[((size_t)bh * 128 + t) * 64 + gg];
        g_norm[idx] = ns;
    }
}

// ---------------- normalize + QKV --------------------------------------------
__global__ void qkv_kernel(const float* __restrict__ wq,
                           const float* __restrict__ wk,
                           const float* __restrict__ wv)
{
    __shared__ float S[64][65];
    int bh = blockIdx.x;
    int tid = threadIdx.x;
    const float* st = g_st + (size_t)bh * 4096;
    const float* nm = g_norm + bh * 64;
    for (int i = tid; i < 4096; i += 256)
        S[i >> 6][i & 63] = st[i] / (nm[i >> 6] + 1e-5f);
    __syncthreads();

    int g = tid >> 2;
    int d0 = (tid & 3) * 16;
    for (int d = d0; d < d0 + 16; ++d) {
        float q = 0.f, k = 0.f, v = 0.f;
        #pragma unroll 8
        for (int c = 0; c < 64; ++c) {
            float s = S[g][c];
            q += s * wq[d * 64 + c];
            k += s * wk[d * 64 + c];
            v += s * wv[d * 64 + c];
        }
        int o = bh * 4096 + g * 64 + d;
        g_q[o] = q; g_k[o] = k; g_v[o] = v;
    }
}

// ---------------- 64x64 attention per (b,h) ----------------------------------
__global__ void attn_kernel()
{
    __shared__ float X[64][65];
    __shared__ float Y[64][65];
    int bh = blockIdx.x;
    int tid = threadIdx.x;
    for (int i = tid; i < 4096; i += 256) {
        X[i >> 6][i & 63] = g_q[bh * 4096 + i];
        Y[i >> 6][i & 63] = g_k[bh * 4096 + i];
    }
    __syncthreads();

    int g = tid >> 2;
    int k0 = (tid & 3) * 16;
    float a[16];
    #pragma unroll
    for (int i = 0; i < 16; ++i) {
        float s = 0.f;
        for (int c = 0; c < 64; ++c) s += X[g][c] * Y[k0 + i][c];
        a[i] = s * 0.125f;
    }
    __syncthreads();
    #pragma unroll
    for (int i = 0; i < 16; ++i) X[g][k0 + i] = a[i];
    for (int i = tid; i < 4096; i += 256)
        Y[i >> 6][i & 63] = g_v[bh * 4096 + i];
    __syncthreads();

    if (tid < 64) {
        float mx = -1e30f;
        for (int k = 0; k < 64; ++k) mx = fmaxf(mx, X[tid][k]);
        float s = 0.f;
        for (int k = 0; k < 64; ++k) { float e = __expf(X[tid][k] - mx); X[tid][k] = e; s += e; }
        float inv = 1.f / s;
        for (int k = 0; k < 64; ++k) X[tid][k] *= inv;
    }
    __syncthreads();

    for (int d = k0; d < k0 + 16; ++d) {
        float o = 0.f;
        for (int k = 0; k < 64; ++k) o += X[g][k] * Y[k][d];
        g_os[bh * 4096 + g * 64 + d] = o;
    }
}

// ---------------- OW: fold out_slice through out_w ---------------------------
// OW[b][h*64+g][d] = sum_c os[bh][g][c] * out_w[d][h*64+c]; grid 64 bh.
__global__ void ow_kernel(const float* __restrict__ out_w)
{
    __shared__ float OS[64][65];
    __shared__ float W[64][65];
    const int bh = blockIdx.x;
    const int h  = bh & 7;
    const int tid = threadIdx.x;

    for (int i = tid; i < 4096; i += 256)
        OS[i >> 6][i & 63] = g_os[(size_t)bh * 4096 + i];

    const int ty = tid >> 5;         // d-group (8 d's)
    const int tx = tid & 31;         // g-group (2 g's)
    const int dd0 = ty * 8;
    const int gg0 = tx * 2;

    #pragma unroll
    for (int half = 0; half < 2; ++half) {
        const int d0 = half * 64;
        __syncthreads();
        for (int i = tid; i < 4096; i += 256) {
            int dd = i >> 6, c = i & 63;
            W[dd][c] = out_w[(size_t)(d0 + dd) * 512 + h * 64 + c];
        }
        __syncthreads();

        float acc[2][8] = {};
        #pragma unroll 4
        for (int c = 0; c < 64; ++c) {
            float o0 = OS[gg0][c], o1 = OS[gg0 + 1][c];
            #pragma unroll
            for (int dd = 0; dd < 8; ++dd) {
                float wv = W[dd0 + dd][c];
                acc[0][dd] += o0 * wv;
                acc[1][dd] += o1 * wv;
            }
        }
        #pragma unroll
        for (int i = 0; i < 2; ++i) {
            float* dst = g_ow + ((size_t)bh * 64 + gg0 + i) * 128 + d0 + dd0;
            *(float4*)dst = make_float4(acc[i][0], acc[i][1], acc[i][2], acc[i][3]);
            *(float4*)(dst + 4) = make_float4(acc[i][4], acc[i][5], acc[i][6], acc[i][7]);
        }
    }
}

// ---------------- fused final: out = swt^T @ OW + out_b ----------------------
// grid (2048 = 8b x 256 ntiles, 2 dtiles), 256 threads, 64x64 tile, K=512.
__global__ void final_kernel(const float* __restrict__ out_b,
                             float* __restrict__ out)
{
    __shared__ float As[32][68];   // [k][n]
    __shared__ float Bs[32][68];   // [k][d]
    const int b     = blockIdx.x >> 8;
    const int m0    = (blockIdx.x & 255) * 64;
    const int d0    = blockIdx.y * 64;
    const int tid   = threadIdx.x;
    const int ty = tid >> 4, tx = tid & 15;
    float acc[4][4] = {};

    const float* abase = g_swt + (size_t)b * 512 * 16384;
    const float* bbase = g_ow + (size_t)b * 512 * 128;

    for (int k0 = 0; k0 < 512; k0 += 32) {
        #pragma unroll
        for (int i = 0; i < 2; ++i) {
            int f = tid + 256 * i;
            int r = f >> 4, q = f & 15;       // r = kk, q = n4
            float4 v = *(const float4*)(abase + (size_t)(k0 + r) * 16384 + m0 + q * 4);
            *(float4*)&As[r][q * 4] = v;
        }
        #pragma unroll
        for (int i = 0; i < 2; ++i) {
            int f = tid + 256 * i;
            int r = f >> 4, q = f & 15;       // r = kk, q = d4
            float4 v = *(const float4*)(bbase + (size_t)(k0 + r) * 128 + d0 + q * 4);
            *(float4*)&Bs[r][q * 4] = v;
        }
        __syncthreads();
        #pragma unroll
        for (int kk = 0; kk < 32; ++kk) {
            float4 a  = *(const float4*)&As[kk][ty * 4];
            float4 bv = *(const float4*)&Bs[kk][tx * 4];
            acc[0][0] += a.x * bv.x; acc[0][1] += a.x * bv.y; acc[0][2] += a.x * bv.z; acc[0][3] += a.x * bv.w;
            acc[1][0] += a.y * bv.x; acc[1][1] += a.y * bv.y; acc[1][2] += a.y * bv.z; acc[1][3] += a.y * bv.w;
            acc[2][0] += a.z * bv.x; acc[2][1] += a.z * bv.y; acc[2][2] += a.z * bv.z; acc[2][3] += a.z * bv.w;
            acc[3][0] += a.w * bv.x; acc[3][1] += a.w * bv.y; acc[3][2] += a.w * bv.z; acc[3][3] += a.w * bv.w;
        }
        __syncthreads();
    }
    #pragma unroll
    for (int i = 0; i < 4; ++i) {
        int n = m0 + ty * 4 + i;
        float* o = out + ((size_t)(b * N_ + n)) * 128 + d0 + tx * 4;
        #pragma unroll
        for (int j = 0; j < 4; ++j)
            o[j] = acc[i][j] + __ldg(out_b + d0 + tx * 4 + j);
    }
}

// ---------------- launch ------------------------------------------------------
extern "C" void kernel_launch(void* const* d_in, const int* in_sizes, int n_in,
                              void* d_out, int out_size)
{
    const float* x          = (const float*)d_in[0];
    const float* conv_fx_w  = (const float*)d_in[1];
    const float* conv_fx_b  = (const float*)d_in[2];
    const float* conv_x_w   = (const float*)d_in[3];
    const float* conv_x_b   = (const float*)d_in[4];
    const float* slice_w    = (const float*)d_in[5];
    const float* slice_b    = (const float*)d_in[6];
    const float* temperature= (const float*)d_in[7];
    const float* wq         = (const float*)d_in[8];
    const float* wk         = (const float*)d_in[9];
    const float* wv         = (const float*)d_in[10];
    const float* out_w      = (const float*)d_in[11];
    const float* out_b      = (const float*)d_in[12];
    float* out = (float*)d_out;

    cudaFuncSetAttribute(conv_mma_kernel,
                         cudaFuncAttributeMaxDynamicSharedMemorySize, 165888);
    cudaFuncSetAttribute(sliceweights_kernel,
                         cudaFuncAttributeMaxDynamicSharedMemorySize, 53248);
    cudaFuncSetAttribute(slicetoken_kernel,
                         cudaFuncAttributeMaxDynamicSharedMemorySize, 69632);

    wprep_kernel<<<4608, 256>>>(conv_fx_w, conv_x_w);
    wprep_x_kernel<<<16384, 256>>>(x);
    conv_mma_kernel<<<dim3(1024, 4), 256, 165888>>>(conv_fx_b, conv_x_b);
    sliceweights_kernel<<<dim3(1024, 8), 256, 53248>>>(slice_w, slice_b, temperature);
    slicetoken_kernel<<<dim3(64, 16), 256, 69632>>>();
    reduce_token_kernel<<<512, 512>>>();
    qkv_kernel<<<64, 256>>>(wq, wk, wv);
    attn_kernel<<<64, 256>>>();
    ow_kernel<<<64, 256>>>(out_w);
    final_kernel<<<dim3(2048, 2), 256>>>(out_b, out);
}